// round 1
// baseline (speedup 1.0000x reference)
#include <cuda_runtime.h>

#define HH 128
#define WW 128
#define CH 64
#define BATCH 4
#define NOFF 18
#define EPS 1e-5f

// ---------------- scratch (no mallocs allowed) ----------------
__device__ __align__(16) float g_xnhwc[BATCH*HH*WW*CH];
__device__ __align__(16) float g_y1   [BATCH*HH*WW*CH];
__device__ __align__(16) float g_off  [BATCH*HH*WW*NOFF];
__device__ __align__(16) float g_wt1  [576*64];
__device__ __align__(16) float g_wt2  [576*64];

// ---------------- f32x2 helpers (sm_100+ packed fp32 FMA) ----------------
static __device__ __forceinline__ unsigned long long pack2(float a, float b){
    unsigned long long r; asm("mov.b64 %0,{%1,%2};" : "=l"(r) : "f"(a), "f"(b)); return r;
}
static __device__ __forceinline__ void fma2(unsigned long long& d, unsigned long long a, unsigned long long b){
    asm("fma.rn.f32x2 %0,%1,%2,%0;" : "+l"(d) : "l"(a), "l"(b));
}
static __device__ __forceinline__ float2 unpack2(unsigned long long v){
    float lo, hi; asm("mov.b64 {%0,%1},%2;" : "=f"(lo), "=f"(hi) : "l"(v));
    return make_float2(lo, hi);
}

// ---------------- NCHW -> NHWC transpose ----------------
__global__ void k_nchw2nhwc(const float* __restrict__ x, float* __restrict__ xn){
    __shared__ float tile[64*129];
    int b = blockIdx.x >> 7;
    int h = blockIdx.x & 127;
    const float* src = x + (b*CH*HH + 0)*WW + h*WW; // + c*HH*WW
    for(int i = threadIdx.x; i < CH*WW; i += blockDim.x){
        int c = i >> 7, w = i & 127;
        tile[c*129 + w] = src[c*HH*WW + w];
    }
    __syncthreads();
    float* dst = xn + ((b*HH + h)*WW)*CH;
    for(int i = threadIdx.x; i < CH*WW; i += blockDim.x){
        int w = i >> 6, c = i & 63;
        dst[w*CH + c] = tile[c*129 + w];
    }
}

// ---------------- weight transpose: w[o][c][ky][kx] -> wt[(k*64+c)*64+o] ----------------
__global__ void k_prep_wt(const float* __restrict__ w, float* __restrict__ wt){
    int i = blockIdx.x*blockDim.x + threadIdx.x;
    if(i >= 576*64) return;
    int o  = i & 63;
    int ck = i >> 6;
    int k  = ck >> 6;
    int c  = ck & 63;
    wt[i] = w[(o*64 + c)*9 + k];
}

// ---------------- offset conv: 3x3, 64->18, zero pad, direct conv ----------------
// grid (HH/2, BATCH), block 128.  Thread t handles pixels (h0,w=t) and (h0+1,w=t).
#define XT_STRIDE_ROW 132
#define XT_STRIDE_C   (4*132)
#define SMEM_OFFK ((CH*XT_STRIDE_C + 9*64*18)*4)

__global__ void __launch_bounds__(128,1) k_offconv(
    const float* __restrict__ xn, const float* __restrict__ woff,
    const float* __restrict__ boff, float* __restrict__ off)
{
    extern __shared__ float sm[];
    float* xt  = sm;                 // [c][4 rows][132 cols]
    float* wsm = sm + CH*XT_STRIDE_C; // [k][c][18]

    int b  = blockIdx.y;
    int h0 = blockIdx.x*2;

    // load input tile: rows h0-1..h0+2, cols -1..128, all 64 ch (zero pad)
    for(int i = threadIdx.x; i < 4*130*16; i += 128){
        int f4   = i & 15;
        int rest = i >> 4;
        int col  = rest % 130;   // = w+1
        int row  = rest / 130;   // = h - (h0-1)
        int hh = h0 - 1 + row;
        int ww = col - 1;
        float4 v = make_float4(0.f,0.f,0.f,0.f);
        if(hh >= 0 && hh < HH && ww >= 0 && ww < WW)
            v = *(const float4*)(xn + ((b*HH + hh)*WW + ww)*CH + f4*4);
        int cb = f4*4;
        xt[(cb+0)*XT_STRIDE_C + row*XT_STRIDE_ROW + col] = v.x;
        xt[(cb+1)*XT_STRIDE_C + row*XT_STRIDE_ROW + col] = v.y;
        xt[(cb+2)*XT_STRIDE_C + row*XT_STRIDE_ROW + col] = v.z;
        xt[(cb+3)*XT_STRIDE_C + row*XT_STRIDE_ROW + col] = v.w;
    }
    // load offset weights: woff[oc][c][ky][kx] -> wsm[(k*64+c)*18 + oc]
    for(int e = threadIdx.x; e < 18*64*9; e += 128){
        int oc  = e / 576;
        int rem = e % 576;
        int c   = rem / 9;
        int k   = rem % 9;
        wsm[(k*64 + c)*18 + oc] = woff[e];
    }
    __syncthreads();

    int w = threadIdx.x;
    unsigned long long acc[2][9];
    #pragma unroll
    for(int p = 0; p < 2; p++)
        #pragma unroll
        for(int j = 0; j < 9; j++) acc[p][j] = 0ull;

    #pragma unroll
    for(int k = 0; k < 9; k++){
        const int ky = k/3, kx = k%3;
        const float* wbase = wsm + k*64*18;
        #pragma unroll 4
        for(int c = 0; c < 64; c++){
            float s0 = xt[c*XT_STRIDE_C + (0+ky)*XT_STRIDE_ROW + (w+kx)];
            float s1 = xt[c*XT_STRIDE_C + (1+ky)*XT_STRIDE_ROW + (w+kx)];
            unsigned long long p0 = pack2(s0,s0);
            unsigned long long p1 = pack2(s1,s1);
            const unsigned long long* wp = (const unsigned long long*)(wbase + c*18);
            #pragma unroll
            for(int j = 0; j < 9; j++){
                unsigned long long wv = wp[j];
                fma2(acc[0][j], wv, p0);
                fma2(acc[1][j], wv, p1);
            }
        }
    }

    #pragma unroll
    for(int p = 0; p < 2; p++){
        float* dst = off + ((b*HH + (h0+p))*WW + w)*NOFF;
        #pragma unroll
        for(int j = 0; j < 9; j++){
            float2 v = unpack2(acc[p][j]);
            dst[2*j]   = v.x + __ldg(&boff[2*j]);
            dst[2*j+1] = v.y + __ldg(&boff[2*j+1]);
        }
    }
}

// ---------------- main DCN: gather (bilinear, deformable) + GEMM + BN + ReLU ----------------
// grid (WW/32, HH, BATCH), block 256. Tile = 32 pixels along w.
// smem: s[32][584] im2col (k-major: idx = k*64+c), wc[64][64] weight K-chunk.
#define S_STRIDE 584
#define SMEM_DCN ((32*S_STRIDE + 64*64)*4)

template<bool NCHW_OUT>
__global__ void __launch_bounds__(256,2) k_dcn(
    const float* __restrict__ xn, const float* __restrict__ off,
    const float* __restrict__ wt,
    const float* __restrict__ gam, const float* __restrict__ bet,
    const float* __restrict__ mu,  const float* __restrict__ var,
    float* __restrict__ out)
{
    extern __shared__ float sm[];
    float* s  = sm;               // 32*584
    float* wc = sm + 32*S_STRIDE; // 64*64

    const int b  = blockIdx.z;
    const int h  = blockIdx.y;
    const int w0 = blockIdx.x*32;
    const int p  = threadIdx.x >> 3;   // pixel in tile
    const int gq = threadIdx.x & 7;    // channel group (8 ch) / output group (8 out)
    const int w  = w0 + p;

    // ---------- Phase 1: deformable bilinear gather into s[p][k*64+c] ----------
    {
        const float* offp = off + ((b*HH + h)*WW + w)*NOFF;
        const float* xb   = xn + ((size_t)b)*HH*WW*CH + gq*8;
        float* srow = s + p*S_STRIDE;
        #pragma unroll
        for(int k = 0; k < 9; k++){
            float dy = __ldg(&offp[2*k]);
            float dx = __ldg(&offp[2*k+1]);
            float py = (float)(h + k/3 - 1) + dy;
            float px = (float)(w + k%3 - 1) + dx;
            float y0f = floorf(py), x0f = floorf(px);
            float wy1 = py - y0f,  wx1 = px - x0f;
            float wy0 = 1.f - wy1, wx0 = 1.f - wx1;
            float y1f = y0f + 1.f, x1f = x0f + 1.f;
            bool vy0 = (y0f >= 0.f) && (y0f <= 127.f);
            bool vy1 = (y1f >= 0.f) && (y1f <= 127.f);
            bool vx0 = (x0f >= 0.f) && (x0f <= 127.f);
            bool vx1 = (x1f >= 0.f) && (x1f <= 127.f);
            int yi0 = (int)fminf(fmaxf(y0f,0.f),127.f);
            int yi1 = (int)fminf(fmaxf(y1f,0.f),127.f);
            int xi0 = (int)fminf(fmaxf(x0f,0.f),127.f);
            int xi1 = (int)fminf(fmaxf(x1f,0.f),127.f);
            float w00 = (vy0 && vx0) ? wy0*wx0 : 0.f;
            float w01 = (vy0 && vx1) ? wy0*wx1 : 0.f;
            float w10 = (vy1 && vx0) ? wy1*wx0 : 0.f;
            float w11 = (vy1 && vx1) ? wy1*wx1 : 0.f;
            const float4* p00 = (const float4*)(xb + (yi0*WW + xi0)*CH);
            const float4* p01 = (const float4*)(xb + (yi0*WW + xi1)*CH);
            const float4* p10 = (const float4*)(xb + (yi1*WW + xi0)*CH);
            const float4* p11 = (const float4*)(xb + (yi1*WW + xi1)*CH);
            float4* dst = (float4*)(srow + k*64 + gq*8);
            #pragma unroll
            for(int q = 0; q < 2; q++){
                float4 a = __ldg(p00+q), bb = __ldg(p01+q);
                float4 c = __ldg(p10+q), d  = __ldg(p11+q);
                float4 r;
                r.x = w00*a.x + w01*bb.x + w10*c.x + w11*d.x;
                r.y = w00*a.y + w01*bb.y + w10*c.y + w11*d.y;
                r.z = w00*a.z + w01*bb.z + w10*c.z + w11*d.z;
                r.w = w00*a.w + w01*bb.w + w10*c.w + w11*d.w;
                dst[q] = r;
            }
        }
    }

    // ---------- Phase 2: out[p][o] = sum_ck s[p][ck] * wt[ck][o], packed f32x2 ----------
    unsigned long long acc[4] = {0ull,0ull,0ull,0ull};
    const float* srow = s + p*S_STRIDE;
    #pragma unroll 1
    for(int kc = 0; kc < 9; kc++){
        __syncthreads();
        const float4* src  = (const float4*)(wt + kc*4096);
        float4*       dstw = (float4*)wc;
        #pragma unroll
        for(int j = 0; j < 4; j++)
            dstw[threadIdx.x + j*256] = __ldg(src + threadIdx.x + j*256);
        __syncthreads();
        const float* sk = srow + kc*64;
        #pragma unroll 8
        for(int r = 0; r < 64; r++){
            float sv = sk[r];
            unsigned long long sp = pack2(sv, sv);
            const unsigned long long* wp = (const unsigned long long*)(wc + r*64 + gq*8);
            fma2(acc[0], wp[0], sp);
            fma2(acc[1], wp[1], sp);
            fma2(acc[2], wp[2], sp);
            fma2(acc[3], wp[3], sp);
        }
    }

    // ---------- Epilogue: BN + ReLU ----------
    float res[8];
    #pragma unroll
    for(int j = 0; j < 4; j++){
        float2 v = unpack2(acc[j]);
        int o0 = gq*8 + 2*j;
        int o1 = o0 + 1;
        float inv0 = __ldg(&gam[o0]) * rsqrtf(__ldg(&var[o0]) + EPS);
        float inv1 = __ldg(&gam[o1]) * rsqrtf(__ldg(&var[o1]) + EPS);
        float bb0  = __ldg(&bet[o0]) - __ldg(&mu[o0]) * inv0;
        float bb1  = __ldg(&bet[o1]) - __ldg(&mu[o1]) * inv1;
        res[2*j]   = fmaxf(v.x*inv0 + bb0, 0.f);
        res[2*j+1] = fmaxf(v.y*inv1 + bb1, 0.f);
    }
    if(NCHW_OUT){
        #pragma unroll
        for(int j = 0; j < 8; j++){
            int o = gq*8 + j;
            out[((b*CH + o)*HH + h)*WW + w] = res[j];
        }
    } else {
        float4* d = (float4*)(out + ((b*HH + h)*WW + w)*CH + gq*8);
        d[0] = make_float4(res[0], res[1], res[2], res[3]);
        d[1] = make_float4(res[4], res[5], res[6], res[7]);
    }
}

// ---------------- launcher ----------------
extern "C" void kernel_launch(void* const* d_in, const int* in_sizes, int n_in,
                              void* d_out, int out_size)
{
    const float* x     = (const float*)d_in[0];
    const float* woff1 = (const float*)d_in[1];
    const float* boff1 = (const float*)d_in[2];
    const float* w1    = (const float*)d_in[3];
    const float* g1    = (const float*)d_in[4];
    const float* be1   = (const float*)d_in[5];
    const float* m1    = (const float*)d_in[6];
    const float* v1    = (const float*)d_in[7];
    const float* woff2 = (const float*)d_in[8];
    const float* boff2 = (const float*)d_in[9];
    const float* w2    = (const float*)d_in[10];
    const float* g2    = (const float*)d_in[11];
    const float* be2   = (const float*)d_in[12];
    const float* m2    = (const float*)d_in[13];
    const float* v2    = (const float*)d_in[14];
    float* out = (float*)d_out;

    float *xn, *y1, *offb, *wt1, *wt2;
    cudaGetSymbolAddress((void**)&xn,   g_xnhwc);
    cudaGetSymbolAddress((void**)&y1,   g_y1);
    cudaGetSymbolAddress((void**)&offb, g_off);
    cudaGetSymbolAddress((void**)&wt1,  g_wt1);
    cudaGetSymbolAddress((void**)&wt2,  g_wt2);

    cudaFuncSetAttribute(k_offconv,     cudaFuncAttributeMaxDynamicSharedMemorySize, SMEM_OFFK);
    cudaFuncSetAttribute(k_dcn<false>,  cudaFuncAttributeMaxDynamicSharedMemorySize, SMEM_DCN);
    cudaFuncSetAttribute(k_dcn<true>,   cudaFuncAttributeMaxDynamicSharedMemorySize, SMEM_DCN);

    // weight prep
    k_prep_wt<<<144, 256>>>(w1, wt1);
    k_prep_wt<<<144, 256>>>(w2, wt2);

    // layer 1
    k_nchw2nhwc<<<BATCH*HH, 256>>>(x, xn);
    k_offconv<<<dim3(HH/2, BATCH), 128, SMEM_OFFK>>>(xn, woff1, boff1, offb);
    k_dcn<false><<<dim3(WW/32, HH, BATCH), 256, SMEM_DCN>>>(xn, offb, wt1, g1, be1, m1, v1, y1);

    // layer 2 (writes NCHW straight to d_out)
    k_offconv<<<dim3(HH/2, BATCH), 128, SMEM_OFFK>>>(y1, woff2, boff2, offb);
    k_dcn<true><<<dim3(WW/32, HH, BATCH), 256, SMEM_DCN>>>(y1, offb, wt2, g2, be2, m2, v2, out);
}

// round 2
// speedup vs baseline: 1.9939x; 1.9939x over previous
#include <cuda_runtime.h>

#define HH 128
#define WW 128
#define CH 64
#define BATCH 4
#define EPS 1e-5f

// ---------------- scratch (no mallocs allowed) ----------------
__device__ __align__(16) float g_xnhwc[BATCH*HH*WW*CH];
__device__ __align__(16) float g_y1   [BATCH*HH*WW*CH];
__device__ __align__(16) float g_off  [BATCH*HH*WW*18];
__device__ __align__(16) float g_wt1  [576*64];
__device__ __align__(16) float g_wt2  [576*64];
__device__ __align__(16) float g_bn   [256];

// ---------------- f32x2 helpers ----------------
static __device__ __forceinline__ unsigned long long pack2(float a, float b){
    unsigned long long r; asm("mov.b64 %0,{%1,%2};" : "=l"(r) : "f"(a), "f"(b)); return r;
}
static __device__ __forceinline__ void fma2(unsigned long long& d, unsigned long long a, unsigned long long b){
    asm("fma.rn.f32x2 %0,%1,%2,%0;" : "+l"(d) : "l"(a), "l"(b));
}
static __device__ __forceinline__ float2 unpack2(unsigned long long v){
    float lo, hi; asm("mov.b64 {%0,%1},%2;" : "=f"(lo), "=f"(hi) : "l"(v));
    return make_float2(lo, hi);
}

// ---------------- NCHW -> NHWC transpose ----------------
__global__ void k_nchw2nhwc(const float* __restrict__ x, float* __restrict__ xn){
    __shared__ float tile[64*129];
    int b = blockIdx.x >> 7;
    int h = blockIdx.x & 127;
    const float* src = x + (b*CH*HH)*WW + h*WW;
    for(int i = threadIdx.x; i < CH*WW; i += blockDim.x){
        int c = i >> 7, w = i & 127;
        tile[c*129 + w] = src[c*HH*WW + w];
    }
    __syncthreads();
    float* dst = xn + ((b*HH + h)*WW)*CH;
    for(int i = threadIdx.x; i < CH*WW; i += blockDim.x){
        int w = i >> 6, c = i & 63;
        dst[w*CH + c] = tile[c*129 + w];
    }
}

// ---------------- weight transpose: w[o][c][k] -> wt[(k*64+c)*64+o] ----------------
__global__ void k_prep_wt(const float* __restrict__ w, float* __restrict__ wt){
    int i = blockIdx.x*blockDim.x + threadIdx.x;
    if(i >= 576*64) return;
    int o  = i & 63;
    int ck = i >> 6;
    int k  = ck >> 6;
    int c  = ck & 63;
    wt[i] = w[(o*64 + c)*9 + k];
}

// ---------------- BN constant prep ----------------
__global__ void k_prep_bn(const float* g1, const float* be1, const float* m1, const float* v1,
                          const float* g2, const float* be2, const float* m2, const float* v2,
                          float* bn){
    int i = threadIdx.x; // 64 threads
    float i1 = g1[i] * rsqrtf(v1[i] + EPS);
    bn[i]      = i1;
    bn[64+i]   = be1[i] - m1[i]*i1;
    float i2 = g2[i] * rsqrtf(v2[i] + EPS);
    bn[128+i]  = i2;
    bn[192+i]  = be2[i] - m2[i]*i2;
}

// ---------------- offset conv v2: 3x3, 64->18 ----------------
// grid (2*HH, BATCH), block 128, tile = 64 px of one row.
// Thread = (pg 0..15 -> 4 px, og 0..7 -> out-pair og; og==0 also out-pair 8).
#define XTC 204   /* channel stride in xtile floats: 3 rows * 68 */
#define OFF_SMEM ((64*XTC + 10368)*4)

__global__ void __launch_bounds__(128,2) k_offconv(
    const float* __restrict__ xn, const float* __restrict__ woff,
    const float* __restrict__ boff, float* __restrict__ off)
{
    extern __shared__ float sm[];
    float* xt = sm;              // [c][3 rows (stride 68)][66 cols]
    float* ws = sm + 64*XTC;     // [(k*64+c)*18 + oc]

    const int b  = blockIdx.y;
    const int h  = blockIdx.x >> 1;
    const int w0 = (blockIdx.x & 1) * 64;

    // load x tile: rows h-1..h+1, cols w0-1..w0+64, all 64 ch (zero pad)
    for(int i = threadIdx.x; i < 3168; i += 128){
        int f4   = i & 15;
        int rest = i >> 4;
        int col  = rest % 66;
        int row  = rest / 66;
        int hh = h - 1 + row;
        int ww = w0 - 1 + col;
        float4 v = make_float4(0.f,0.f,0.f,0.f);
        if(hh >= 0 && hh < HH && ww >= 0 && ww < WW)
            v = *(const float4*)(xn + ((b*HH + hh)*WW + ww)*CH + f4*4);
        int cb = f4*4;
        xt[(cb+0)*XTC + row*68 + col] = v.x;
        xt[(cb+1)*XTC + row*68 + col] = v.y;
        xt[(cb+2)*XTC + row*68 + col] = v.z;
        xt[(cb+3)*XTC + row*68 + col] = v.w;
    }
    // load offset weights: woff[(oc*64+c)*9+k] -> ws[(k*64+c)*18 + oc]
    for(int e = threadIdx.x; e < 10368; e += 128){
        int oc  = e / 576;
        int rem = e % 576;
        int c   = rem / 9;
        int kk  = rem % 9;
        ws[(kk*64 + c)*18 + oc] = woff[e];
    }
    __syncthreads();

    const int pg  = threadIdx.x >> 3;
    const int og  = threadIdx.x & 7;
    const int px0 = pg*4;
    const int j1  = og ? og : 8;

    unsigned long long acc[4][2];
    #pragma unroll
    for(int l = 0; l < 4; l++){ acc[l][0] = 0ull; acc[l][1] = 0ull; }

    #pragma unroll
    for(int k = 0; k < 9; k++){
        const int ky = k/3, kx = k%3;
        const float* xb = xt + ky*68 + px0 + kx;
        const float* wb = ws + k*64*18;
        #pragma unroll 4
        for(int c = 0; c < 64; c++){
            float s0 = xb[c*XTC + 0];
            float s1 = xb[c*XTC + 1];
            float s2 = xb[c*XTC + 2];
            float s3 = xb[c*XTC + 3];
            unsigned long long wp0 = *(const unsigned long long*)(wb + c*18 + 2*og);
            unsigned long long wp1 = *(const unsigned long long*)(wb + c*18 + 2*j1);
            unsigned long long sp0 = pack2(s0,s0);
            unsigned long long sp1 = pack2(s1,s1);
            unsigned long long sp2 = pack2(s2,s2);
            unsigned long long sp3 = pack2(s3,s3);
            fma2(acc[0][0], wp0, sp0); fma2(acc[0][1], wp1, sp0);
            fma2(acc[1][0], wp0, sp1); fma2(acc[1][1], wp1, sp1);
            fma2(acc[2][0], wp0, sp2); fma2(acc[2][1], wp1, sp2);
            fma2(acc[3][0], wp0, sp3); fma2(acc[3][1], wp1, sp3);
        }
    }

    float b0 = __ldg(&boff[2*og]), b1 = __ldg(&boff[2*og+1]);
    float b8 = __ldg(&boff[16]),   b9 = __ldg(&boff[17]);
    #pragma unroll
    for(int l = 0; l < 4; l++){
        float* dst = off + ((b*HH + h)*WW + (w0 + px0 + l))*18;
        float2 v0 = unpack2(acc[l][0]);
        dst[2*og]   = v0.x + b0;
        dst[2*og+1] = v0.y + b1;
        if(og == 0){
            float2 v1 = unpack2(acc[l][1]);
            dst[16] = v1.x + b8;
            dst[17] = v1.y + b9;
        }
    }
}

// ---------------- main DCN v2: K-chunked gather + register-tiled GEMM ----------------
// grid (2, HH, BATCH), block 256. Tile = 64 px, 64 out.
// Per k-tap: stage s[c 0..63][px 0..63] (transposed im2col) + w chunk [c][o], then GEMM.
// Thread GEMM tile: 4 px (as 2 f32x2 pairs) x 4 out.
template<bool NCHW_OUT>
__global__ void __launch_bounds__(256,3) k_dcn(
    const float* __restrict__ xn, const float* __restrict__ off,
    const float* __restrict__ wt, const float* __restrict__ bn,
    float* __restrict__ out)
{
    __shared__ float s  [64*64];
    __shared__ float wsm[64*64];
    __shared__ float off_s[64*18];

    const int b  = blockIdx.z;
    const int h  = blockIdx.y;
    const int w0 = blockIdx.x * 64;
    const int tid = threadIdx.x;

    // load offsets for the 64 pixels
    {
        const float* src = off + ((b*HH + h)*WW + w0)*18;
        for(int i = tid; i < 64*18; i += 256) off_s[i] = src[i];
    }

    // gather mapping
    const int gpx = tid & 63;
    const int cq  = tid >> 6;          // channel quarter (16 ch)
    const float* xb = xn + ((size_t)b)*HH*WW*CH + cq*16;
    const float fh = (float)h;
    const float fw = (float)(w0 + gpx);

    // GEMM mapping
    const int pg = tid >> 4;           // 0..15 -> px 4*pg..+3
    const int og = tid & 15;           // 0..15 -> out 4*og..+3

    unsigned long long acc[2][4];
    #pragma unroll
    for(int i = 0; i < 2; i++)
        #pragma unroll
        for(int j = 0; j < 4; j++) acc[i][j] = 0ull;

    const float4* wt4 = (const float4*)wt;

    #pragma unroll 1
    for(int k = 0; k < 9; k++){
        __syncthreads();
        // stage weight chunk [64c][64o]
        {
            float4* d = (float4*)wsm;
            const float4* srcw = wt4 + k*1024;
            #pragma unroll
            for(int j = 0; j < 4; j++)
                d[tid + j*256] = __ldg(srcw + tid + j*256);
        }
        // deformable bilinear gather -> s[c][px]
        {
            float dy = off_s[gpx*18 + 2*k];
            float dx = off_s[gpx*18 + 2*k + 1];
            float py  = fh + (float)(k/3 - 1) + dy;
            float pxx = fw + (float)(k%3 - 1) + dx;
            float y0f = floorf(py), x0f = floorf(pxx);
            float wy1 = py - y0f,  wx1 = pxx - x0f;
            float wy0 = 1.f - wy1, wx0 = 1.f - wx1;
            float y1f = y0f + 1.f, x1f = x0f + 1.f;
            bool vy0 = (y0f >= 0.f) && (y0f <= 127.f);
            bool vy1 = (y1f >= 0.f) && (y1f <= 127.f);
            bool vx0 = (x0f >= 0.f) && (x0f <= 127.f);
            bool vx1 = (x1f >= 0.f) && (x1f <= 127.f);
            int yi0 = (int)fminf(fmaxf(y0f,0.f),127.f);
            int yi1 = (int)fminf(fmaxf(y1f,0.f),127.f);
            int xi0 = (int)fminf(fmaxf(x0f,0.f),127.f);
            int xi1 = (int)fminf(fmaxf(x1f,0.f),127.f);
            float w00 = (vy0 && vx0) ? wy0*wx0 : 0.f;
            float w01 = (vy0 && vx1) ? wy0*wx1 : 0.f;
            float w10 = (vy1 && vx0) ? wy1*wx0 : 0.f;
            float w11 = (vy1 && vx1) ? wy1*wx1 : 0.f;
            const float4* p00 = (const float4*)(xb + (yi0*WW + xi0)*CH);
            const float4* p01 = (const float4*)(xb + (yi0*WW + xi1)*CH);
            const float4* p10 = (const float4*)(xb + (yi1*WW + xi0)*CH);
            const float4* p11 = (const float4*)(xb + (yi1*WW + xi1)*CH);
            #pragma unroll
            for(int q = 0; q < 4; q++){
                float4 a = __ldg(p00+q), bb = __ldg(p01+q);
                float4 c = __ldg(p10+q), d  = __ldg(p11+q);
                float4 r;
                r.x = w00*a.x + w01*bb.x + w10*c.x + w11*d.x;
                r.y = w00*a.y + w01*bb.y + w10*c.y + w11*d.y;
                r.z = w00*a.z + w01*bb.z + w10*c.z + w11*d.z;
                r.w = w00*a.w + w01*bb.w + w10*c.w + w11*d.w;
                int rb = cq*16 + q*4;
                s[(rb+0)*64 + gpx] = r.x;
                s[(rb+1)*64 + gpx] = r.y;
                s[(rb+2)*64 + gpx] = r.z;
                s[(rb+3)*64 + gpx] = r.w;
            }
        }
        __syncthreads();
        // GEMM chunk: acc[pp][o] over r = 0..63
        const float* srow = s   + 4*pg;
        const float* wrow = wsm + 4*og;
        #pragma unroll 4
        for(int r = 0; r < 64; r++){
            unsigned long long s01 = *(const unsigned long long*)(srow + r*64);
            unsigned long long s23 = *(const unsigned long long*)(srow + r*64 + 2);
            float4 wv = *(const float4*)(wrow + r*64);
            unsigned long long wp0 = pack2(wv.x, wv.x);
            unsigned long long wp1 = pack2(wv.y, wv.y);
            unsigned long long wp2 = pack2(wv.z, wv.z);
            unsigned long long wp3 = pack2(wv.w, wv.w);
            fma2(acc[0][0], s01, wp0); fma2(acc[1][0], s23, wp0);
            fma2(acc[0][1], s01, wp1); fma2(acc[1][1], s23, wp1);
            fma2(acc[0][2], s01, wp2); fma2(acc[1][2], s23, wp2);
            fma2(acc[0][3], s01, wp3); fma2(acc[1][3], s23, wp3);
        }
    }

    // ---------- Epilogue: BN + ReLU ----------
    float iv[4], bc[4];
    {
        float4 a = *(const float4*)(bn + 4*og);
        float4 c = *(const float4*)(bn + 64 + 4*og);
        iv[0]=a.x; iv[1]=a.y; iv[2]=a.z; iv[3]=a.w;
        bc[0]=c.x; bc[1]=c.y; bc[2]=c.z; bc[3]=c.w;
    }
    float res[4][4];
    #pragma unroll
    for(int pp = 0; pp < 2; pp++)
        #pragma unroll
        for(int o = 0; o < 4; o++){
            float2 v = unpack2(acc[pp][o]);
            res[pp*2+0][o] = fmaxf(v.x*iv[o] + bc[o], 0.f);
            res[pp*2+1][o] = fmaxf(v.y*iv[o] + bc[o], 0.f);
        }

    if(NCHW_OUT){
        #pragma unroll
        for(int o = 0; o < 4; o++){
            int oc = 4*og + o;
            float* base = out + (((size_t)b*CH + oc)*HH + h)*WW + w0 + 4*pg;
            *(float2*)(base)     = make_float2(res[0][o], res[1][o]);
            *(float2*)(base + 2) = make_float2(res[2][o], res[3][o]);
        }
    } else {
        #pragma unroll
        for(int l = 0; l < 4; l++){
            float4* d = (float4*)(out + ((b*HH + h)*WW + (w0 + 4*pg + l))*CH + 4*og);
            *d = make_float4(res[l][0], res[l][1], res[l][2], res[l][3]);
        }
    }
}

// ---------------- launcher ----------------
extern "C" void kernel_launch(void* const* d_in, const int* in_sizes, int n_in,
                              void* d_out, int out_size)
{
    const float* x     = (const float*)d_in[0];
    const float* woff1 = (const float*)d_in[1];
    const float* boff1 = (const float*)d_in[2];
    const float* w1    = (const float*)d_in[3];
    const float* g1    = (const float*)d_in[4];
    const float* be1   = (const float*)d_in[5];
    const float* m1    = (const float*)d_in[6];
    const float* v1    = (const float*)d_in[7];
    const float* woff2 = (const float*)d_in[8];
    const float* boff2 = (const float*)d_in[9];
    const float* w2    = (const float*)d_in[10];
    const float* g2    = (const float*)d_in[11];
    const float* be2   = (const float*)d_in[12];
    const float* m2    = (const float*)d_in[13];
    const float* v2    = (const float*)d_in[14];
    float* out = (float*)d_out;

    float *xn, *y1, *offb, *wt1, *wt2, *bn;
    cudaGetSymbolAddress((void**)&xn,   g_xnhwc);
    cudaGetSymbolAddress((void**)&y1,   g_y1);
    cudaGetSymbolAddress((void**)&offb, g_off);
    cudaGetSymbolAddress((void**)&wt1,  g_wt1);
    cudaGetSymbolAddress((void**)&wt2,  g_wt2);
    cudaGetSymbolAddress((void**)&bn,   g_bn);

    cudaFuncSetAttribute(k_offconv, cudaFuncAttributeMaxDynamicSharedMemorySize, OFF_SMEM);

    // 1..4: prep (positions k_dcn layer-1 as launch #6 for ncu -s 5 -c 1)
    k_nchw2nhwc<<<BATCH*HH, 256>>>(x, xn);
    k_prep_wt<<<144, 256>>>(w1, wt1);
    k_prep_wt<<<144, 256>>>(w2, wt2);
    k_prep_bn<<<1, 64>>>(g1, be1, m1, v1, g2, be2, m2, v2, bn);

    // layer 1
    k_offconv<<<dim3(2*HH, BATCH), 128, OFF_SMEM>>>(xn, woff1, boff1, offb);
    k_dcn<false><<<dim3(2, HH, BATCH), 256>>>(xn, offb, wt1, bn, y1);

    // layer 2 (writes NCHW straight to d_out)
    k_offconv<<<dim3(2*HH, BATCH), 128, OFF_SMEM>>>(y1, woff2, boff2, offb);
    k_dcn<true><<<dim3(2, HH, BATCH), 256>>>(y1, offb, wt2, bn + 128, out);
}

// round 4
// speedup vs baseline: 3.5597x; 1.7853x over previous
#include <cuda_runtime.h>
#include <cuda_bf16.h>
#include <cstdint>

#define HH 128
#define WW 128
#define CH 64
#define BATCH 4
#define EPS 1e-5f

// ---------------- scratch (no mallocs allowed) ----------------
__device__ __align__(16) float g_xnhwc[BATCH*HH*WW*CH];
__device__ __align__(16) float g_y1   [BATCH*HH*WW*CH];
__device__ __align__(16) float g_off  [BATCH*HH*WW*18];
// per layer: 9 taps x (hi tile 64x64 bf16 swizzled [o][c], mid tile) = 9*16KB
__device__ __align__(1024) __nv_bfloat16 g_wtb1[9*2*64*64];
__device__ __align__(1024) __nv_bfloat16 g_wtb2[9*2*64*64];
__device__ __align__(16) float g_bn[256];

// ---------------- f32x2 helpers (offconv) ----------------
static __device__ __forceinline__ unsigned long long pack2(float a, float b){
    unsigned long long r; asm("mov.b64 %0,{%1,%2};" : "=l"(r) : "f"(a), "f"(b)); return r;
}
static __device__ __forceinline__ void fma2(unsigned long long& d, unsigned long long a, unsigned long long b){
    asm("fma.rn.f32x2 %0,%1,%2,%0;" : "+l"(d) : "l"(a), "l"(b));
}
static __device__ __forceinline__ float2 unpack2(unsigned long long v){
    float lo, hi; asm("mov.b64 {%0,%1},%2;" : "=f"(lo), "=f"(hi) : "l"(v));
    return make_float2(lo, hi);
}

// ---------------- tensor-core helpers (baseline PTX: sm_80+) ----------------
static __device__ __forceinline__ uint32_t smem_to_u32(const void* p){
    uint32_t a;
    asm("{ .reg .u64 t; cvta.to.shared.u64 t, %1; cvt.u32.u64 %0, t; }" : "=r"(a) : "l"(p));
    return a;
}
#define SWZ128(o) ((o) ^ (((o) >> 3) & 0x70))

#define LDSM4(r, a) \
    asm volatile("ldmatrix.sync.aligned.m8n8.x4.shared.b16 {%0,%1,%2,%3}, [%4];" \
        : "=r"((r)[0]), "=r"((r)[1]), "=r"((r)[2]), "=r"((r)[3]) : "r"(a))

static __device__ __forceinline__ void mma16816(float* d, const uint32_t* a, uint32_t b0, uint32_t b1){
    asm volatile("mma.sync.aligned.m16n8k16.row.col.f32.bf16.bf16.f32 "
        "{%0,%1,%2,%3},{%4,%5,%6,%7},{%8,%9},{%0,%1,%2,%3};"
        : "+f"(d[0]), "+f"(d[1]), "+f"(d[2]), "+f"(d[3])
        : "r"(a[0]), "r"(a[1]), "r"(a[2]), "r"(a[3]), "r"(b0), "r"(b1));
}

// ---------------- prep: weight bf16-split swizzled tiles + BN constants ----------------
__global__ void k_prep(const float* __restrict__ w1, const float* __restrict__ w2,
                       const float* g1, const float* be1, const float* m1, const float* v1,
                       const float* g2, const float* be2, const float* m2, const float* v2)
{
    int i = blockIdx.x*blockDim.x + threadIdx.x;
    if(i < 73728){
        int L   = i / 36864;
        int rem = i % 36864;
        int k = rem >> 12;          // tap
        int o = (rem >> 6) & 63;
        int c = rem & 63;
        const float* w = L ? w2 : w1;
        float val = w[(o*64 + c)*9 + k];
        __nv_bfloat16 hb = __float2bfloat16(val);
        float hf = __bfloat162float(hb);
        __nv_bfloat16 mb = __float2bfloat16(val - hf);
        char* dst = (char*)(L ? g_wtb2 : g_wtb1);
        int sw = SWZ128(o*128 + c*2);
        *(__nv_bfloat16*)(dst + k*16384 +        sw) = hb;
        *(__nv_bfloat16*)(dst + k*16384 + 8192 + sw) = mb;
    }
    if(blockIdx.x == 0 && threadIdx.x < 64){
        int t = threadIdx.x;
        float i1 = g1[t] * rsqrtf(v1[t] + EPS);
        g_bn[t]      = i1;
        g_bn[64+t]   = be1[t] - m1[t]*i1;
        float i2 = g2[t] * rsqrtf(v2[t] + EPS);
        g_bn[128+t]  = i2;
        g_bn[192+t]  = be2[t] - m2[t]*i2;
    }
}

// ---------------- NCHW -> NHWC transpose ----------------
__global__ void k_nchw2nhwc(const float* __restrict__ x, float* __restrict__ xn){
    __shared__ float tile[64*129];
    int b = blockIdx.x >> 7;
    int h = blockIdx.x & 127;
    const float* src = x + (b*CH*HH)*WW + h*WW;
    for(int i = threadIdx.x; i < CH*WW; i += blockDim.x){
        int c = i >> 7, w = i & 127;
        tile[c*129 + w] = src[c*HH*WW + w];
    }
    __syncthreads();
    float* dst = xn + ((b*HH + h)*WW)*CH;
    for(int i = threadIdx.x; i < CH*WW; i += blockDim.x){
        int w = i >> 6, c = i & 63;
        dst[w*CH + c] = tile[c*129 + w];
    }
}

// ---------------- offset conv: 3x3, 64->18 (fp32 f32x2) ----------------
#define XTC 204
#define OFF_SMEM ((64*XTC + 10368)*4)

__global__ void __launch_bounds__(128,2) k_offconv(
    const float* __restrict__ xn, const float* __restrict__ woff,
    const float* __restrict__ boff, float* __restrict__ off)
{
    extern __shared__ float sm[];
    float* xt = sm;
    float* ws = sm + 64*XTC;

    const int b  = blockIdx.y;
    const int h  = blockIdx.x >> 1;
    const int w0 = (blockIdx.x & 1) * 64;

    for(int i = threadIdx.x; i < 3168; i += 128){
        int f4   = i & 15;
        int rest = i >> 4;
        int col  = rest % 66;
        int row  = rest / 66;
        int hh = h - 1 + row;
        int ww = w0 - 1 + col;
        float4 v = make_float4(0.f,0.f,0.f,0.f);
        if(hh >= 0 && hh < HH && ww >= 0 && ww < WW)
            v = *(const float4*)(xn + ((b*HH + hh)*WW + ww)*CH + f4*4);
        int cb = f4*4;
        xt[(cb+0)*XTC + row*68 + col] = v.x;
        xt[(cb+1)*XTC + row*68 + col] = v.y;
        xt[(cb+2)*XTC + row*68 + col] = v.z;
        xt[(cb+3)*XTC + row*68 + col] = v.w;
    }
    for(int e = threadIdx.x; e < 10368; e += 128){
        int oc  = e / 576;
        int rem = e % 576;
        int c   = rem / 9;
        int kk  = rem % 9;
        ws[(kk*64 + c)*18 + oc] = woff[e];
    }
    __syncthreads();

    const int pg  = threadIdx.x >> 3;
    const int og  = threadIdx.x & 7;
    const int px0 = pg*4;
    const int j1  = og ? og : 8;

    unsigned long long acc[4][2];
    #pragma unroll
    for(int l = 0; l < 4; l++){ acc[l][0] = 0ull; acc[l][1] = 0ull; }

    #pragma unroll
    for(int k = 0; k < 9; k++){
        const int ky = k/3, kx = k%3;
        const float* xb = xt + ky*68 + px0 + kx;
        const float* wb = ws + k*64*18;
        #pragma unroll 4
        for(int c = 0; c < 64; c++){
            float s0 = xb[c*XTC + 0];
            float s1 = xb[c*XTC + 1];
            float s2 = xb[c*XTC + 2];
            float s3 = xb[c*XTC + 3];
            unsigned long long wp0 = *(const unsigned long long*)(wb + c*18 + 2*og);
            unsigned long long wp1 = *(const unsigned long long*)(wb + c*18 + 2*j1);
            unsigned long long sp0 = pack2(s0,s0);
            unsigned long long sp1 = pack2(s1,s1);
            unsigned long long sp2 = pack2(s2,s2);
            unsigned long long sp3 = pack2(s3,s3);
            fma2(acc[0][0], wp0, sp0); fma2(acc[0][1], wp1, sp0);
            fma2(acc[1][0], wp0, sp1); fma2(acc[1][1], wp1, sp1);
            fma2(acc[2][0], wp0, sp2); fma2(acc[2][1], wp1, sp2);
            fma2(acc[3][0], wp0, sp3); fma2(acc[3][1], wp1, sp3);
        }
    }

    float b0 = __ldg(&boff[2*og]), b1 = __ldg(&boff[2*og+1]);
    float b8 = __ldg(&boff[16]),   b9 = __ldg(&boff[17]);
    #pragma unroll
    for(int l = 0; l < 4; l++){
        float* dst = off + ((b*HH + h)*WW + (w0 + px0 + l))*18;
        float2 v0 = unpack2(acc[l][0]);
        dst[2*og]   = v0.x + b0;
        dst[2*og+1] = v0.y + b1;
        if(og == 0){
            float2 v1 = unpack2(acc[l][1]);
            dst[16] = v1.x + b8;
            dst[17] = v1.y + b9;
        }
    }
}

// ---------------- main DCN: mma.sync bf16 3-split GEMM ----------------
// grid = BATCH*HH (one block per image row): M=128 px, N=64 out, K=9 taps x 64ch
// smem byte offsets
#define OFFS_OFF   0          /* 128*18*4 = 9216 */
#define A_HI_OFF   10240      /* 128x64 bf16 = 16384, SW128 [px][ch] */
#define A_MID_OFF  26624
#define B_HI_OFF   43008      /* 64x64 bf16 = 8192, SW128 [out][ch] */
#define B_MID_OFF  51200
#define DCN_SMEM   59392

template<bool NCHW_OUT>
__global__ void __launch_bounds__(256,2) k_dcn(
    const float* __restrict__ xn, const float* __restrict__ off,
    const __nv_bfloat16* __restrict__ wtb, const float* __restrict__ bn,
    float* __restrict__ out)
{
    extern __shared__ char smc[];
    const uint32_t smem_base = smem_to_u32(smc);
    float* off_s = (float*)(smc + OFFS_OFF);

    const int b = blockIdx.x >> 7;
    const int h = blockIdx.x & 127;
    const int tid = threadIdx.x;
    const int wid = tid >> 5;
    const int lid = tid & 31;

    // load offsets for the row (128 px x 18)
    {
        const float* src = off + ((b*HH + h)*WW)*18;
        #pragma unroll
        for(int j = 0; j < 9; j++) off_s[tid + j*256] = src[tid + j*256];
    }
    __syncthreads();

    // gather mapping
    const float* xb = xn + (size_t)b*HH*WW*CH;
    const int q  = tid & 15;           // 16B channel chunk
    const int pg = tid >> 4;           // pixel group: px = pg*8 + i
    const float fh = (float)h;

    // mma mapping: warp (4 x 2) grid of 32x32 tiles
    const int m0 = (wid >> 1) * 32;
    const int n0 = (wid & 1) * 32;

    // precompute ldmatrix lane addresses (swizzle = col ^ ((row&7)<<4))
    uint32_t aBase[2], aXor[2];
    #pragma unroll
    for(int mi = 0; mi < 2; mi++){
        int r = m0 + mi*16 + (lid & 15);
        aBase[mi] = smem_base + A_HI_OFF + r*128;
        aXor[mi]  = (r & 7) << 4;
    }
    const uint32_t aKh = (lid >> 4) * 16;
    uint32_t bBase[2], bXor[2];
    #pragma unroll
    for(int ni = 0; ni < 2; ni++){
        int r = n0 + ni*16 + (lid & 7) + ((lid >> 4) << 3);
        bBase[ni] = smem_base + B_HI_OFF + r*128;
        bXor[ni]  = (r & 7) << 4;
    }
    const uint32_t bKh = ((lid >> 3) & 1) * 16;

    float acc[2][4][4];
    #pragma unroll
    for(int mi = 0; mi < 2; mi++)
        #pragma unroll
        for(int ni = 0; ni < 4; ni++)
            #pragma unroll
            for(int j = 0; j < 4; j++) acc[mi][ni][j] = 0.f;

    #pragma unroll 1
    for(int k = 0; k < 9; k++){
        // stage B tiles (hi+mid, 16KB) for this tap
        {
            const uint4* bs = (const uint4*)wtb + k*1024;
            uint4* bd = (uint4*)(smc + B_HI_OFF);
            #pragma unroll
            for(int j = 0; j < 4; j++) bd[tid + j*256] = __ldg(bs + tid + j*256);
        }

        // deformable bilinear gather -> A_hi / A_mid ([px][ch], SW128)
        const int ky = k/3 - 1, kx = k%3 - 1;
        #pragma unroll 2
        for(int i = 0; i < 8; i++){
            int px = pg*8 + i;
            float dy = off_s[px*18 + 2*k];
            float dx = off_s[px*18 + 2*k + 1];
            float py  = fh + (float)ky + dy;
            float pxx = (float)(px + kx) + dx;
            float y0f = floorf(py), x0f = floorf(pxx);
            float wy1 = py - y0f,  wx1 = pxx - x0f;
            float wy0 = 1.f - wy1, wx0 = 1.f - wx1;
            float y1f = y0f + 1.f, x1f = x0f + 1.f;
            bool vy0 = (y0f >= 0.f) && (y0f <= 127.f);
            bool vy1 = (y1f >= 0.f) && (y1f <= 127.f);
            bool vx0 = (x0f >= 0.f) && (x0f <= 127.f);
            bool vx1 = (x1f >= 0.f) && (x1f <= 127.f);
            int yi0 = (int)fminf(fmaxf(y0f,0.f),127.f);
            int yi1 = (int)fminf(fmaxf(y1f,0.f),127.f);
            int xi0 = (int)fminf(fmaxf(x0f,0.f),127.f);
            int xi1 = (int)fminf(fmaxf(x1f,0.f),127.f);
            float w00 = (vy0 && vx0) ? wy0*wx0 : 0.f;
            float w01 = (vy0 && vx1) ? wy0*wx1 : 0.f;
            float w10 = (vy1 && vx0) ? wy1*wx0 : 0.f;
            float w11 = (vy1 && vx1) ? wy1*wx1 : 0.f;
            float4 a = __ldg((const float4*)(xb + (yi0*WW + xi0)*CH) + q);
            float4 bb= __ldg((const float4*)(xb + (yi0*WW + xi1)*CH) + q);
            float4 c = __ldg((const float4*)(xb + (yi1*WW + xi0)*CH) + q);
            float4 d = __ldg((const float4*)(xb + (yi1*WW + xi1)*CH) + q);
            float4 r;
            r.x = w00*a.x + w01*bb.x + w10*c.x + w11*d.x;
            r.y = w00*a.y + w01*bb.y + w10*c.y + w11*d.y;
            r.z = w00*a.z + w01*bb.z + w10*c.z + w11*d.z;
            r.w = w00*a.w + w01*bb.w + w10*c.w + w11*d.w;
            // bf16 split: hi + mid
            __nv_bfloat162 h0 = __float22bfloat162_rn(make_float2(r.x, r.y));
            __nv_bfloat162 h1 = __float22bfloat162_rn(make_float2(r.z, r.w));
            float2 f0 = __bfloat1622float2(h0);
            float2 f1 = __bfloat1622float2(h1);
            __nv_bfloat162 m0b = __float22bfloat162_rn(make_float2(r.x - f0.x, r.y - f0.y));
            __nv_bfloat162 m1b = __float22bfloat162_rn(make_float2(r.z - f1.x, r.w - f1.y));
            int sw = SWZ128(px*128 + q*8);
            uint2 uh, um;
            uh.x = *(uint32_t*)&h0; uh.y = *(uint32_t*)&h1;
            um.x = *(uint32_t*)&m0b; um.y = *(uint32_t*)&m1b;
            *(uint2*)(smc + A_HI_OFF  + sw) = uh;
            *(uint2*)(smc + A_MID_OFF + sw) = um;
        }
        __syncthreads();

        // tensor-core GEMM for this tap: 4 k16 steps
        #pragma unroll
        for(int ks = 0; ks < 4; ks++){
            uint32_t ahi[2][4], ami[2][4], bhi[2][4], bmi[2][4];
            uint32_t ca = ks*32 + aKh;
            #pragma unroll
            for(int mi = 0; mi < 2; mi++){
                uint32_t ad = aBase[mi] + (ca ^ aXor[mi]);
                LDSM4(ahi[mi], ad);
                LDSM4(ami[mi], ad + (A_MID_OFF - A_HI_OFF));
            }
            uint32_t cb = ks*32 + bKh;
            #pragma unroll
            for(int ni = 0; ni < 2; ni++){
                uint32_t bd = bBase[ni] + (cb ^ bXor[ni]);
                LDSM4(bhi[ni], bd);
                LDSM4(bmi[ni], bd + (B_MID_OFF - B_HI_OFF));
            }
            #pragma unroll
            for(int mi = 0; mi < 2; mi++)
                #pragma unroll
                for(int n8 = 0; n8 < 4; n8++){
                    uint32_t bh0 = bhi[n8>>1][(n8&1)*2], bh1 = bhi[n8>>1][(n8&1)*2+1];
                    uint32_t bm0 = bmi[n8>>1][(n8&1)*2], bm1 = bmi[n8>>1][(n8&1)*2+1];
                    mma16816(acc[mi][n8], ahi[mi], bh0, bh1);
                    mma16816(acc[mi][n8], ahi[mi], bm0, bm1);
                    mma16816(acc[mi][n8], ami[mi], bh0, bh1);
                }
        }
        __syncthreads();
    }

    // BN constants into smem (off_s reused)
    if(tid < 128) off_s[tid] = bn[tid];
    __syncthreads();

    // epilogue: BN + ReLU + store
    #pragma unroll
    for(int mi = 0; mi < 2; mi++){
        int r0 = m0 + mi*16 + (lid >> 2);
        int r1 = r0 + 8;
        #pragma unroll
        for(int n8 = 0; n8 < 4; n8++){
            int c0 = n0 + n8*8 + (lid & 3)*2;
            float iv0 = off_s[c0],     iv1 = off_s[c0+1];
            float bc0 = off_s[64+c0],  bc1 = off_s[64+c0+1];
            float v00 = fmaxf(acc[mi][n8][0]*iv0 + bc0, 0.f);
            float v01 = fmaxf(acc[mi][n8][1]*iv1 + bc1, 0.f);
            float v10 = fmaxf(acc[mi][n8][2]*iv0 + bc0, 0.f);
            float v11 = fmaxf(acc[mi][n8][3]*iv1 + bc1, 0.f);
            if(NCHW_OUT){
                float* o0 = out + (((size_t)b*CH + c0)*HH + h)*WW;
                float* o1 = out + (((size_t)b*CH + c0+1)*HH + h)*WW;
                o0[r0] = v00; o1[r0] = v01;
                o0[r1] = v10; o1[r1] = v11;
            } else {
                float* base = out + ((size_t)(b*HH + h)*WW)*CH;
                *(float2*)(base + r0*CH + c0) = make_float2(v00, v01);
                *(float2*)(base + r1*CH + c0) = make_float2(v10, v11);
            }
        }
    }
}

// ---------------- launcher ----------------
extern "C" void kernel_launch(void* const* d_in, const int* in_sizes, int n_in,
                              void* d_out, int out_size)
{
    const float* x     = (const float*)d_in[0];
    const float* woff1 = (const float*)d_in[1];
    const float* boff1 = (const float*)d_in[2];
    const float* w1    = (const float*)d_in[3];
    const float* g1    = (const float*)d_in[4];
    const float* be1   = (const float*)d_in[5];
    const float* m1    = (const float*)d_in[6];
    const float* v1    = (const float*)d_in[7];
    const float* woff2 = (const float*)d_in[8];
    const float* boff2 = (const float*)d_in[9];
    const float* w2    = (const float*)d_in[10];
    const float* g2    = (const float*)d_in[11];
    const float* be2   = (const float*)d_in[12];
    const float* m2    = (const float*)d_in[13];
    const float* v2    = (const float*)d_in[14];
    float* out = (float*)d_out;

    float *xn, *y1, *offb, *bn;
    __nv_bfloat16 *wtb1, *wtb2;
    cudaGetSymbolAddress((void**)&xn,   g_xnhwc);
    cudaGetSymbolAddress((void**)&y1,   g_y1);
    cudaGetSymbolAddress((void**)&offb, g_off);
    cudaGetSymbolAddress((void**)&wtb1, g_wtb1);
    cudaGetSymbolAddress((void**)&wtb2, g_wtb2);
    cudaGetSymbolAddress((void**)&bn,   g_bn);

    cudaFuncSetAttribute(k_offconv,    cudaFuncAttributeMaxDynamicSharedMemorySize, OFF_SMEM);
    cudaFuncSetAttribute(k_dcn<false>, cudaFuncAttributeMaxDynamicSharedMemorySize, DCN_SMEM);
    cudaFuncSetAttribute(k_dcn<true>,  cudaFuncAttributeMaxDynamicSharedMemorySize, DCN_SMEM);

    // launch order: k_dcn layer-1 is launch #4 (ncu effective skip = 3)
    k_prep<<<288, 256>>>(w1, w2, g1, be1, m1, v1, g2, be2, m2, v2);
    k_nchw2nhwc<<<BATCH*HH, 256>>>(x, xn);
    k_offconv<<<dim3(2*HH, BATCH), 128, OFF_SMEM>>>(xn, woff1, boff1, offb);
    k_dcn<false><<<BATCH*HH, 256, DCN_SMEM>>>(xn, offb, wtb1, bn, y1);

    k_offconv<<<dim3(2*HH, BATCH), 128, OFF_SMEM>>>(y1, woff2, boff2, offb);
    k_dcn<true><<<BATCH*HH, 256, DCN_SMEM>>>(y1, offb, wtb2, bn + 128, out);
}

// round 5
// speedup vs baseline: 5.1172x; 1.4375x over previous
#include <cuda_runtime.h>
#include <cuda_bf16.h>
#include <cstdint>

#define HH 128
#define WW 128
#define CH 64
#define BATCH 4
#define EPS 1e-5f

// ---------------- scratch (no mallocs allowed) ----------------
__device__ __align__(16) float g_xnhwc[BATCH*HH*WW*CH];
__device__ __align__(16) float g_y1   [BATCH*HH*WW*CH];
__device__ __align__(16) float g_off  [BATCH*HH*WW*18];
// main weights: 9 taps x (hi 64x64 bf16 SW128 [o][c], mid) per layer
__device__ __align__(1024) __nv_bfloat16 g_wtb1[9*2*64*64];
__device__ __align__(1024) __nv_bfloat16 g_wtb2[9*2*64*64];
// offset-conv weights: 9 taps x (hi 32x64, mid 32x64) per layer (rows >=18 zero)
__device__ __align__(1024) __nv_bfloat16 g_wob1[9*2*32*64];
__device__ __align__(1024) __nv_bfloat16 g_wob2[9*2*32*64];
__device__ __align__(16) float g_bn[256];

// ---------------- tensor-core helpers (baseline PTX: sm_80+) ----------------
static __device__ __forceinline__ uint32_t smem_to_u32(const void* p){
    uint32_t a;
    asm("{ .reg .u64 t; cvta.to.shared.u64 t, %1; cvt.u32.u64 %0, t; }" : "=r"(a) : "l"(p));
    return a;
}
#define SWZ128(o) ((o) ^ (((o) >> 3) & 0x70))

#define LDSM4(r, a) \
    asm volatile("ldmatrix.sync.aligned.m8n8.x4.shared.b16 {%0,%1,%2,%3}, [%4];" \
        : "=r"((r)[0]), "=r"((r)[1]), "=r"((r)[2]), "=r"((r)[3]) : "r"(a))

static __device__ __forceinline__ void mma16816(float* d, const uint32_t* a, uint32_t b0, uint32_t b1){
    asm volatile("mma.sync.aligned.m16n8k16.row.col.f32.bf16.bf16.f32 "
        "{%0,%1,%2,%3},{%4,%5,%6,%7},{%8,%9},{%0,%1,%2,%3};"
        : "+f"(d[0]), "+f"(d[1]), "+f"(d[2]), "+f"(d[3])
        : "r"(a[0]), "r"(a[1]), "r"(a[2]), "r"(a[3]), "r"(b0), "r"(b1));
}

// ---------------- prep: weight bf16-split swizzled tiles + BN constants ----------------
__global__ void k_prep(const float* __restrict__ w1, const float* __restrict__ w2,
                       const float* __restrict__ woff1, const float* __restrict__ woff2,
                       const float* g1, const float* be1, const float* m1, const float* v1,
                       const float* g2, const float* be2, const float* m2, const float* v2)
{
    int i = blockIdx.x*blockDim.x + threadIdx.x;
    if(i < 73728){
        // main conv weights: [(o*64+c)*9+k] -> per-tap [o][c] SW128 hi/mid
        int L   = i / 36864;
        int rem = i % 36864;
        int k = rem >> 12;
        int o = (rem >> 6) & 63;
        int c = rem & 63;
        const float* w = L ? w2 : w1;
        float val = w[(o*64 + c)*9 + k];
        __nv_bfloat16 hb = __float2bfloat16(val);
        float hf = __bfloat162float(hb);
        __nv_bfloat16 mb = __float2bfloat16(val - hf);
        char* dst = (char*)(L ? g_wtb2 : g_wtb1);
        int sw = SWZ128(o*128 + c*2);
        *(__nv_bfloat16*)(dst + k*16384 +        sw) = hb;
        *(__nv_bfloat16*)(dst + k*16384 + 8192 + sw) = mb;
    } else if(i < 110592){
        // offset conv weights: 18 real rows, padded to 32
        int j   = i - 73728;
        int L   = j / 18432;
        int rem = j % 18432;
        int k = rem >> 11;
        int o = (rem >> 6) & 31;
        int c = rem & 63;
        const float* w = L ? woff2 : woff1;
        float val = (o < 18) ? w[(o*64 + c)*9 + k] : 0.f;
        __nv_bfloat16 hb = __float2bfloat16(val);
        float hf = __bfloat162float(hb);
        __nv_bfloat16 mb = __float2bfloat16(val - hf);
        char* dst = (char*)(L ? g_wob2 : g_wob1);
        int sw = SWZ128(o*128 + c*2);
        *(__nv_bfloat16*)(dst + k*8192 +        sw) = hb;
        *(__nv_bfloat16*)(dst + k*8192 + 4096 + sw) = mb;
    }
    if(blockIdx.x == 0 && threadIdx.x < 64){
        int t = threadIdx.x;
        float i1 = g1[t] * rsqrtf(v1[t] + EPS);
        g_bn[t]      = i1;
        g_bn[64+t]   = be1[t] - m1[t]*i1;
        float i2 = g2[t] * rsqrtf(v2[t] + EPS);
        g_bn[128+t]  = i2;
        g_bn[192+t]  = be2[t] - m2[t]*i2;
    }
}

// ---------------- NCHW -> NHWC transpose ----------------
__global__ void k_nchw2nhwc(const float* __restrict__ x, float* __restrict__ xn){
    __shared__ float tile[64*129];
    int b = blockIdx.x >> 7;
    int h = blockIdx.x & 127;
    const float* src = x + (b*CH*HH)*WW + h*WW;
    for(int i = threadIdx.x; i < CH*WW; i += blockDim.x){
        int c = i >> 7, w = i & 127;
        tile[c*129 + w] = src[c*HH*WW + w];
    }
    __syncthreads();
    float* dst = xn + ((b*HH + h)*WW)*CH;
    for(int i = threadIdx.x; i < CH*WW; i += blockDim.x){
        int w = i >> 6, c = i & 63;
        dst[w*CH + c] = tile[c*129 + w];
    }
}

// ---------------- offset conv via tensor cores ----------------
// grid = BATCH*HH; M=128 px, N=24 (18 used), K=9x64. Warp = 16px x 24out.
#define OT_A_HI  0
#define OT_A_MID 16384
#define OT_B_HI  32768
#define OT_B_MID 36864
#define OT_SMEM  40960

__global__ void __launch_bounds__(256,3) k_offt(
    const float* __restrict__ xn, const __nv_bfloat16* __restrict__ wob,
    const float* __restrict__ boff, float* __restrict__ off)
{
    extern __shared__ char smc[];
    const uint32_t smem_base = smem_to_u32(smc);

    const int b = blockIdx.x >> 7;
    const int h = blockIdx.x & 127;
    const int tid = threadIdx.x;
    const int wid = tid >> 5;
    const int lid = tid & 31;
    const int m0 = wid * 16;

    // ldmatrix lane addresses
    uint32_t aBase, aXor;
    {
        int r = m0 + (lid & 15);
        aBase = smem_base + OT_A_HI + r*128;
        aXor  = (r & 7) << 4;
    }
    const uint32_t aKh = (lid >> 4) * 16;
    uint32_t bBase[2], bXor[2];
    #pragma unroll
    for(int ni = 0; ni < 2; ni++){
        int r = ni*16 + (lid & 7) + ((lid >> 4) << 3);
        bBase[ni] = smem_base + OT_B_HI + r*128;
        bXor[ni]  = (r & 7) << 4;
    }
    const uint32_t bKh = ((lid >> 3) & 1) * 16;

    float acc[3][4];
    #pragma unroll
    for(int n8 = 0; n8 < 3; n8++)
        #pragma unroll
        for(int j = 0; j < 4; j++) acc[n8][j] = 0.f;

    #pragma unroll 1
    for(int k = 0; k < 9; k++){
        __syncthreads();
        // stage B tap tile (8KB)
        {
            const uint4* bs = (const uint4*)wob + k*512;
            uint4* bd = (uint4*)(smc + OT_B_HI);
            bd[tid]       = __ldg(bs + tid);
            bd[tid + 256] = __ldg(bs + tid + 256);
        }
        // build A: shifted copy of input row (zero pad)
        const int hh = h + k/3 - 1;
        const int kx = k%3 - 1;
        const bool hv = (hh >= 0) && (hh < HH);
        const float* rowp = xn + ((size_t)(b*HH + hh)*WW)*CH;
        #pragma unroll 2
        for(int i = 0; i < 8; i++){
            int idx = tid + i*256;
            int q  = idx & 15;
            int px = idx >> 4;
            int ww = px + kx;
            float4 v = make_float4(0.f,0.f,0.f,0.f);
            if(hv && ww >= 0 && ww < WW)
                v = __ldg((const float4*)(rowp + ww*CH) + q);
            __nv_bfloat162 h0 = __float22bfloat162_rn(make_float2(v.x, v.y));
            __nv_bfloat162 h1 = __float22bfloat162_rn(make_float2(v.z, v.w));
            float2 f0 = __bfloat1622float2(h0);
            float2 f1 = __bfloat1622float2(h1);
            __nv_bfloat162 m0b = __float22bfloat162_rn(make_float2(v.x - f0.x, v.y - f0.y));
            __nv_bfloat162 m1b = __float22bfloat162_rn(make_float2(v.z - f1.x, v.w - f1.y));
            int sw = SWZ128(px*128 + q*8);
            uint2 uh, um;
            uh.x = *(uint32_t*)&h0;  uh.y = *(uint32_t*)&h1;
            um.x = *(uint32_t*)&m0b; um.y = *(uint32_t*)&m1b;
            *(uint2*)(smc + OT_A_HI  + sw) = uh;
            *(uint2*)(smc + OT_A_MID + sw) = um;
        }
        __syncthreads();

        #pragma unroll
        for(int ks = 0; ks < 4; ks++){
            uint32_t ahi[4], ami[4], bhi[2][4], bmi[2][4];
            uint32_t ad = aBase + ((ks*32 + aKh) ^ aXor);
            LDSM4(ahi, ad);
            LDSM4(ami, ad + (OT_A_MID - OT_A_HI));
            uint32_t cb = ks*32 + bKh;
            #pragma unroll
            for(int ni = 0; ni < 2; ni++){
                uint32_t bd = bBase[ni] + (cb ^ bXor[ni]);
                LDSM4(bhi[ni], bd);
                LDSM4(bmi[ni], bd + (OT_B_MID - OT_B_HI));
            }
            #pragma unroll
            for(int n8 = 0; n8 < 3; n8++){
                uint32_t bh0 = bhi[n8>>1][(n8&1)*2], bh1 = bhi[n8>>1][(n8&1)*2+1];
                uint32_t bm0 = bmi[n8>>1][(n8&1)*2], bm1 = bmi[n8>>1][(n8&1)*2+1];
                mma16816(acc[n8], ahi, bh0, bh1);
                mma16816(acc[n8], ahi, bm0, bm1);
                mma16816(acc[n8], ami, bh0, bh1);
            }
        }
    }

    // epilogue: bias + store (only c<18)
    const int r0 = m0 + (lid >> 2);
    const int r1 = r0 + 8;
    float* d0 = off + ((size_t)(b*HH + h)*WW + r0)*18;
    float* d1 = off + ((size_t)(b*HH + h)*WW + r1)*18;
    #pragma unroll
    for(int n8 = 0; n8 < 3; n8++){
        int c0 = n8*8 + (lid & 3)*2;
        if(c0 < 18){
            float b0 = __ldg(boff + c0);
            float b1v = __ldg(boff + c0 + 1);
            d0[c0]   = acc[n8][0] + b0;
            d0[c0+1] = acc[n8][1] + b1v;
            d1[c0]   = acc[n8][2] + b0;
            d1[c0+1] = acc[n8][3] + b1v;
        }
    }
}

// ---------------- main DCN: precomputed gather + mma.sync bf16 3-split ----------------
// grid = BATCH*HH; M=128 px, N=64 out, K=9x64.
// smem byte offsets
#define PRE_OFF   0          /* 1152 entries x 32B = 36864 */
#define A_HI_OFF  36864      /* 128x64 bf16 SW128 = 16384 */
#define A_MID_OFF 53248
#define B_HI_OFF  69632      /* 64x64 bf16 SW128 = 8192 */
#define B_MID_OFF 77824
#define DCN_SMEM  86016

template<bool NCHW_OUT>
__global__ void __launch_bounds__(256,2) k_dcn(
    const float* __restrict__ xn, const float* __restrict__ off,
    const __nv_bfloat16* __restrict__ wtb, const float* __restrict__ bn,
    float* __restrict__ out)
{
    extern __shared__ char smc[];
    const uint32_t smem_base = smem_to_u32(smc);

    const int b = blockIdx.x >> 7;
    const int h = blockIdx.x & 127;
    const int tid = threadIdx.x;
    const int wid = tid >> 5;
    const int lid = tid & 31;
    const float fh = (float)h;

    // ---------- precompute bilinear weights + corner byte-offsets ----------
    {
        float4* wtab = (float4*)(smc + PRE_OFF);
        uint4*  itab = (uint4*)(smc + PRE_OFF);
        #pragma unroll 1
        for(int e = tid; e < 1152; e += 256){
            int k  = e >> 7;
            int px = e & 127;
            const float* op = off + ((size_t)(b*HH + h)*WW + px)*18 + 2*k;
            float dy = __ldg(op);
            float dx = __ldg(op + 1);
            float py  = fh + (float)(k/3 - 1) + dy;
            float pxx = (float)(px + k%3 - 1) + dx;
            float y0f = floorf(py), x0f = floorf(pxx);
            float wy1 = py - y0f,  wx1 = pxx - x0f;
            float wy0 = 1.f - wy1, wx0 = 1.f - wx1;
            float y1f = y0f + 1.f, x1f = x0f + 1.f;
            bool vy0 = (y0f >= 0.f) && (y0f <= 127.f);
            bool vy1 = (y1f >= 0.f) && (y1f <= 127.f);
            bool vx0 = (x0f >= 0.f) && (x0f <= 127.f);
            bool vx1 = (x1f >= 0.f) && (x1f <= 127.f);
            int yi0 = (int)fminf(fmaxf(y0f,0.f),127.f);
            int yi1 = (int)fminf(fmaxf(y1f,0.f),127.f);
            int xi0 = (int)fminf(fmaxf(x0f,0.f),127.f);
            int xi1 = (int)fminf(fmaxf(x1f,0.f),127.f);
            float w00 = (vy0 && vx0) ? wy0*wx0 : 0.f;
            float w01 = (vy0 && vx1) ? wy0*wx1 : 0.f;
            float w10 = (vy1 && vx0) ? wy1*wx0 : 0.f;
            float w11 = (vy1 && vx1) ? wy1*wx1 : 0.f;
            wtab[2*e]   = make_float4(w00, w01, w10, w11);
            itab[2*e+1] = make_uint4((uint32_t)yi0*32768u, (uint32_t)xi0*256u,
                                     (uint32_t)yi1*32768u, (uint32_t)xi1*256u);
        }
    }

    // gather mapping
    const char* xq = (const char*)(xn + (size_t)b*HH*WW*CH) + (tid & 15)*16;
    const int q  = tid & 15;
    const int pg = tid >> 4;

    // mma mapping: warp (4 x 2) grid of 32x32 tiles
    const int m0 = (wid >> 1) * 32;
    const int n0 = (wid & 1) * 32;

    uint32_t aBase[2], aXor[2];
    #pragma unroll
    for(int mi = 0; mi < 2; mi++){
        int r = m0 + mi*16 + (lid & 15);
        aBase[mi] = smem_base + A_HI_OFF + r*128;
        aXor[mi]  = (r & 7) << 4;
    }
    const uint32_t aKh = (lid >> 4) * 16;
    uint32_t bBase[2], bXor[2];
    #pragma unroll
    for(int ni = 0; ni < 2; ni++){
        int r = n0 + ni*16 + (lid & 7) + ((lid >> 4) << 3);
        bBase[ni] = smem_base + B_HI_OFF + r*128;
        bXor[ni]  = (r & 7) << 4;
    }
    const uint32_t bKh = ((lid >> 3) & 1) * 16;

    float acc[2][4][4];
    #pragma unroll
    for(int mi = 0; mi < 2; mi++)
        #pragma unroll
        for(int ni = 0; ni < 4; ni++)
            #pragma unroll
            for(int j = 0; j < 4; j++) acc[mi][ni][j] = 0.f;

    const float4* wtab = (const float4*)(smc + PRE_OFF);
    const uint4*  itab = (const uint4*)(smc + PRE_OFF);

    #pragma unroll 1
    for(int k = 0; k < 9; k++){
        __syncthreads();
        // stage B tiles (hi+mid, 16KB)
        {
            const uint4* bs = (const uint4*)wtb + k*1024;
            uint4* bd = (uint4*)(smc + B_HI_OFF);
            #pragma unroll
            for(int j = 0; j < 4; j++) bd[tid + j*256] = __ldg(bs + tid + j*256);
        }
        // lean gather using precomputed table
        #pragma unroll 2
        for(int i = 0; i < 8; i++){
            int px = pg*8 + i;
            int e  = k*128 + px;
            float4 wv = wtab[2*e];
            uint4  id = itab[2*e+1];
            float4 a  = __ldg((const float4*)(xq + id.x + id.y));
            float4 b2 = __ldg((const float4*)(xq + id.x + id.w));
            float4 c  = __ldg((const float4*)(xq + id.z + id.y));
            float4 d  = __ldg((const float4*)(xq + id.z + id.w));
            float4 r;
            r.x = wv.x*a.x + wv.y*b2.x + wv.z*c.x + wv.w*d.x;
            r.y = wv.x*a.y + wv.y*b2.y + wv.z*c.y + wv.w*d.y;
            r.z = wv.x*a.z + wv.y*b2.z + wv.z*c.z + wv.w*d.z;
            r.w = wv.x*a.w + wv.y*b2.w + wv.z*c.w + wv.w*d.w;
            __nv_bfloat162 h0 = __float22bfloat162_rn(make_float2(r.x, r.y));
            __nv_bfloat162 h1 = __float22bfloat162_rn(make_float2(r.z, r.w));
            float2 f0 = __bfloat1622float2(h0);
            float2 f1 = __bfloat1622float2(h1);
            __nv_bfloat162 m0b = __float22bfloat162_rn(make_float2(r.x - f0.x, r.y - f0.y));
            __nv_bfloat162 m1b = __float22bfloat162_rn(make_float2(r.z - f1.x, r.w - f1.y));
            int sw = SWZ128(px*128 + q*8);
            uint2 uh, um;
            uh.x = *(uint32_t*)&h0;  uh.y = *(uint32_t*)&h1;
            um.x = *(uint32_t*)&m0b; um.y = *(uint32_t*)&m1b;
            *(uint2*)(smc + A_HI_OFF  + sw) = uh;
            *(uint2*)(smc + A_MID_OFF + sw) = um;
        }
        __syncthreads();

        // tensor-core GEMM for this tap
        #pragma unroll
        for(int ks = 0; ks < 4; ks++){
            uint32_t ahi[2][4], ami[2][4], bhi[2][4], bmi[2][4];
            uint32_t ca = ks*32 + aKh;
            #pragma unroll
            for(int mi = 0; mi < 2; mi++){
                uint32_t ad = aBase[mi] + (ca ^ aXor[mi]);
                LDSM4(ahi[mi], ad);
                LDSM4(ami[mi], ad + (A_MID_OFF - A_HI_OFF));
            }
            uint32_t cb = ks*32 + bKh;
            #pragma unroll
            for(int ni = 0; ni < 2; ni++){
                uint32_t bd = bBase[ni] + (cb ^ bXor[ni]);
                LDSM4(bhi[ni], bd);
                LDSM4(bmi[ni], bd + (B_MID_OFF - B_HI_OFF));
            }
            #pragma unroll
            for(int mi = 0; mi < 2; mi++)
                #pragma unroll
                for(int n8 = 0; n8 < 4; n8++){
                    uint32_t bh0 = bhi[n8>>1][(n8&1)*2], bh1 = bhi[n8>>1][(n8&1)*2+1];
                    uint32_t bm0 = bmi[n8>>1][(n8&1)*2], bm1 = bmi[n8>>1][(n8&1)*2+1];
                    mma16816(acc[mi][n8], ahi[mi], bh0, bh1);
                    mma16816(acc[mi][n8], ahi[mi], bm0, bm1);
                    mma16816(acc[mi][n8], ami[mi], bh0, bh1);
                }
        }
    }

    // epilogue: BN + ReLU + store
    #pragma unroll
    for(int mi = 0; mi < 2; mi++){
        int r0 = m0 + mi*16 + (lid >> 2);
        int r1 = r0 + 8;
        #pragma unroll
        for(int n8 = 0; n8 < 4; n8++){
            int c0 = n0 + n8*8 + (lid & 3)*2;
            float iv0 = __ldg(bn + c0),      iv1 = __ldg(bn + c0 + 1);
            float bc0 = __ldg(bn + 64 + c0), bc1 = __ldg(bn + 64 + c0 + 1);
            float v00 = fmaxf(acc[mi][n8][0]*iv0 + bc0, 0.f);
            float v01 = fmaxf(acc[mi][n8][1]*iv1 + bc1, 0.f);
            float v10 = fmaxf(acc[mi][n8][2]*iv0 + bc0, 0.f);
            float v11 = fmaxf(acc[mi][n8][3]*iv1 + bc1, 0.f);
            if(NCHW_OUT){
                float* o0 = out + (((size_t)b*CH + c0)*HH + h)*WW;
                float* o1 = out + (((size_t)b*CH + c0+1)*HH + h)*WW;
                o0[r0] = v00; o1[r0] = v01;
                o0[r1] = v10; o1[r1] = v11;
            } else {
                float* base = out + ((size_t)(b*HH + h)*WW)*CH;
                *(float2*)(base + r0*CH + c0) = make_float2(v00, v01);
                *(float2*)(base + r1*CH + c0) = make_float2(v10, v11);
            }
        }
    }
}

// ---------------- launcher ----------------
extern "C" void kernel_launch(void* const* d_in, const int* in_sizes, int n_in,
                              void* d_out, int out_size)
{
    const float* x     = (const float*)d_in[0];
    const float* woff1 = (const float*)d_in[1];
    const float* boff1 = (const float*)d_in[2];
    const float* w1    = (const float*)d_in[3];
    const float* g1    = (const float*)d_in[4];
    const float* be1   = (const float*)d_in[5];
    const float* m1    = (const float*)d_in[6];
    const float* v1    = (const float*)d_in[7];
    const float* woff2 = (const float*)d_in[8];
    const float* boff2 = (const float*)d_in[9];
    const float* w2    = (const float*)d_in[10];
    const float* g2    = (const float*)d_in[11];
    const float* be2   = (const float*)d_in[12];
    const float* m2    = (const float*)d_in[13];
    const float* v2    = (const float*)d_in[14];
    float* out = (float*)d_out;

    float *xn, *y1, *offb, *bn;
    __nv_bfloat16 *wtb1, *wtb2, *wob1, *wob2;
    cudaGetSymbolAddress((void**)&xn,   g_xnhwc);
    cudaGetSymbolAddress((void**)&y1,   g_y1);
    cudaGetSymbolAddress((void**)&offb, g_off);
    cudaGetSymbolAddress((void**)&wtb1, g_wtb1);
    cudaGetSymbolAddress((void**)&wtb2, g_wtb2);
    cudaGetSymbolAddress((void**)&wob1, g_wob1);
    cudaGetSymbolAddress((void**)&wob2, g_wob2);
    cudaGetSymbolAddress((void**)&bn,   g_bn);

    cudaFuncSetAttribute(k_offt,       cudaFuncAttributeMaxDynamicSharedMemorySize, OT_SMEM);
    cudaFuncSetAttribute(k_dcn<false>, cudaFuncAttributeMaxDynamicSharedMemorySize, DCN_SMEM);
    cudaFuncSetAttribute(k_dcn<true>,  cudaFuncAttributeMaxDynamicSharedMemorySize, DCN_SMEM);

    // launch order: k_dcn layer-1 is launch #4 (ncu effective skip = 3)
    k_prep<<<432, 256>>>(w1, w2, woff1, woff2, g1, be1, m1, v1, g2, be2, m2, v2);
    k_nchw2nhwc<<<BATCH*HH, 256>>>(x, xn);
    k_offt<<<BATCH*HH, 256, OT_SMEM>>>(xn, wob1, boff1, offb);
    k_dcn<false><<<BATCH*HH, 256, DCN_SMEM>>>(xn, offb, wtb1, bn, y1);

    k_offt<<<BATCH*HH, 256, OT_SMEM>>>(y1, wob2, boff2, offb);
    k_dcn<true><<<BATCH*HH, 256, DCN_SMEM>>>(y1, offb, wtb2, bn + 128, out);
}

// round 6
// speedup vs baseline: 5.3792x; 1.0512x over previous
#include <cuda_runtime.h>
#include <cuda_bf16.h>
#include <cstdint>

#define HH 128
#define WW 128
#define CH 64
#define BATCH 4
#define EPS 1e-5f

// ---------------- scratch (no mallocs allowed) ----------------
__device__ __align__(16) float g_xnhwc[BATCH*HH*WW*CH];
__device__ __align__(16) float g_y1   [BATCH*HH*WW*CH];
__device__ __align__(16) float g_off  [BATCH*HH*WW*18];
// main weights: 9 taps x (hi 64x64 bf16 SW128 [o][c], mid) per layer
__device__ __align__(1024) __nv_bfloat16 g_wtb1[9*2*64*64];
__device__ __align__(1024) __nv_bfloat16 g_wtb2[9*2*64*64];
// offset-conv weights: 9 taps x (hi 32x64, mid 32x64) per layer (rows >=18 zero)
__device__ __align__(1024) __nv_bfloat16 g_wob1[9*2*32*64];
__device__ __align__(1024) __nv_bfloat16 g_wob2[9*2*32*64];
__device__ __align__(16) float g_bn[256];

// ---------------- tensor-core helpers (baseline PTX: sm_80+) ----------------
static __device__ __forceinline__ uint32_t smem_to_u32(const void* p){
    uint32_t a;
    asm("{ .reg .u64 t; cvta.to.shared.u64 t, %1; cvt.u32.u64 %0, t; }" : "=r"(a) : "l"(p));
    return a;
}
#define SWZ128(o) ((o) ^ (((o) >> 3) & 0x70))

#define LDSM4(r, a) \
    asm volatile("ldmatrix.sync.aligned.m8n8.x4.shared.b16 {%0,%1,%2,%3}, [%4];" \
        : "=r"((r)[0]), "=r"((r)[1]), "=r"((r)[2]), "=r"((r)[3]) : "r"(a))

static __device__ __forceinline__ void mma16816(float* d, const uint32_t* a, uint32_t b0, uint32_t b1){
    asm volatile("mma.sync.aligned.m16n8k16.row.col.f32.bf16.bf16.f32 "
        "{%0,%1,%2,%3},{%4,%5,%6,%7},{%8,%9},{%0,%1,%2,%3};"
        : "+f"(d[0]), "+f"(d[1]), "+f"(d[2]), "+f"(d[3])
        : "r"(a[0]), "r"(a[1]), "r"(a[2]), "r"(a[3]), "r"(b0), "r"(b1));
}

// ---------------- prep: weight bf16-split swizzled tiles + BN constants ----------------
__global__ void k_prep(const float* __restrict__ w1, const float* __restrict__ w2,
                       const float* __restrict__ woff1, const float* __restrict__ woff2,
                       const float* g1, const float* be1, const float* m1, const float* v1,
                       const float* g2, const float* be2, const float* m2, const float* v2)
{
    int i = blockIdx.x*blockDim.x + threadIdx.x;
    if(i < 73728){
        int L   = i / 36864;
        int rem = i % 36864;
        int k = rem >> 12;
        int o = (rem >> 6) & 63;
        int c = rem & 63;
        const float* w = L ? w2 : w1;
        float val = w[(o*64 + c)*9 + k];
        __nv_bfloat16 hb = __float2bfloat16(val);
        float hf = __bfloat162float(hb);
        __nv_bfloat16 mb = __float2bfloat16(val - hf);
        char* dst = (char*)(L ? g_wtb2 : g_wtb1);
        int sw = SWZ128(o*128 + c*2);
        *(__nv_bfloat16*)(dst + k*16384 +        sw) = hb;
        *(__nv_bfloat16*)(dst + k*16384 + 8192 + sw) = mb;
    } else if(i < 110592){
        int j   = i - 73728;
        int L   = j / 18432;
        int rem = j % 18432;
        int k = rem >> 11;
        int o = (rem >> 6) & 31;
        int c = rem & 63;
        const float* w = L ? woff2 : woff1;
        float val = (o < 18) ? w[(o*64 + c)*9 + k] : 0.f;
        __nv_bfloat16 hb = __float2bfloat16(val);
        float hf = __bfloat162float(hb);
        __nv_bfloat16 mb = __float2bfloat16(val - hf);
        char* dst = (char*)(L ? g_wob2 : g_wob1);
        int sw = SWZ128(o*128 + c*2);
        *(__nv_bfloat16*)(dst + k*8192 +        sw) = hb;
        *(__nv_bfloat16*)(dst + k*8192 + 4096 + sw) = mb;
    }
    if(blockIdx.x == 0 && threadIdx.x < 64){
        int t = threadIdx.x;
        float i1 = g1[t] * rsqrtf(v1[t] + EPS);
        g_bn[t]      = i1;
        g_bn[64+t]   = be1[t] - m1[t]*i1;
        float i2 = g2[t] * rsqrtf(v2[t] + EPS);
        g_bn[128+t]  = i2;
        g_bn[192+t]  = be2[t] - m2[t]*i2;
    }
}

// ---------------- NCHW -> NHWC transpose ----------------
__global__ void k_nchw2nhwc(const float* __restrict__ x, float* __restrict__ xn){
    __shared__ float tile[64*129];
    int b = blockIdx.x >> 7;
    int h = blockIdx.x & 127;
    const float* src = x + (b*CH*HH)*WW + h*WW;
    for(int i = threadIdx.x; i < CH*WW; i += blockDim.x){
        int c = i >> 7, w = i & 127;
        tile[c*129 + w] = src[c*HH*WW + w];
    }
    __syncthreads();
    float* dst = xn + ((b*HH + h)*WW)*CH;
    for(int i = threadIdx.x; i < CH*WW; i += blockDim.x){
        int w = i >> 6, c = i & 63;
        dst[w*CH + c] = tile[c*129 + w];
    }
}

// ---------------- offset conv via tensor cores ----------------
#define OT_A_HI  0
#define OT_A_MID 16384
#define OT_B_HI  32768
#define OT_B_MID 36864
#define OT_SMEM  40960

__global__ void __launch_bounds__(256,3) k_offt(
    const float* __restrict__ xn, const __nv_bfloat16* __restrict__ wob,
    const float* __restrict__ boff, float* __restrict__ off)
{
    extern __shared__ char smc[];
    const uint32_t smem_base = smem_to_u32(smc);

    const int b = blockIdx.x >> 7;
    const int h = blockIdx.x & 127;
    const int tid = threadIdx.x;
    const int wid = tid >> 5;
    const int lid = tid & 31;
    const int m0 = wid * 16;

    uint32_t aBase, aXor;
    {
        int r = m0 + (lid & 15);
        aBase = smem_base + OT_A_HI + r*128;
        aXor  = (r & 7) << 4;
    }
    const uint32_t aKh = (lid >> 4) * 16;
    uint32_t bBase[2], bXor[2];
    #pragma unroll
    for(int ni = 0; ni < 2; ni++){
        int r = ni*16 + (lid & 7) + ((lid >> 4) << 3);
        bBase[ni] = smem_base + OT_B_HI + r*128;
        bXor[ni]  = (r & 7) << 4;
    }
    const uint32_t bKh = ((lid >> 3) & 1) * 16;

    float acc[3][4];
    #pragma unroll
    for(int n8 = 0; n8 < 3; n8++)
        #pragma unroll
        for(int j = 0; j < 4; j++) acc[n8][j] = 0.f;

    #pragma unroll 1
    for(int k = 0; k < 9; k++){
        __syncthreads();
        {
            const uint4* bs = (const uint4*)wob + k*512;
            uint4* bd = (uint4*)(smc + OT_B_HI);
            bd[tid]       = __ldg(bs + tid);
            bd[tid + 256] = __ldg(bs + tid + 256);
        }
        const int hh = h + k/3 - 1;
        const int kx = k%3 - 1;
        const bool hv = (hh >= 0) && (hh < HH);
        const float* rowp = xn + ((size_t)(b*HH + hh)*WW)*CH;
        #pragma unroll 2
        for(int i = 0; i < 8; i++){
            int idx = tid + i*256;
            int q  = idx & 15;
            int px = idx >> 4;
            int ww = px + kx;
            float4 v = make_float4(0.f,0.f,0.f,0.f);
            if(hv && ww >= 0 && ww < WW)
                v = __ldg((const float4*)(rowp + ww*CH) + q);
            __nv_bfloat162 h0 = __float22bfloat162_rn(make_float2(v.x, v.y));
            __nv_bfloat162 h1 = __float22bfloat162_rn(make_float2(v.z, v.w));
            float2 f0 = __bfloat1622float2(h0);
            float2 f1 = __bfloat1622float2(h1);
            __nv_bfloat162 m0b = __float22bfloat162_rn(make_float2(v.x - f0.x, v.y - f0.y));
            __nv_bfloat162 m1b = __float22bfloat162_rn(make_float2(v.z - f1.x, v.w - f1.y));
            int sw = SWZ128(px*128 + q*8);
            uint2 uh, um;
            uh.x = *(uint32_t*)&h0;  uh.y = *(uint32_t*)&h1;
            um.x = *(uint32_t*)&m0b; um.y = *(uint32_t*)&m1b;
            *(uint2*)(smc + OT_A_HI  + sw) = uh;
            *(uint2*)(smc + OT_A_MID + sw) = um;
        }
        __syncthreads();

        #pragma unroll
        for(int ks = 0; ks < 4; ks++){
            uint32_t ahi[4], ami[4], bhi[2][4], bmi[2][4];
            uint32_t ad = aBase + ((ks*32 + aKh) ^ aXor);
            LDSM4(ahi, ad);
            LDSM4(ami, ad + (OT_A_MID - OT_A_HI));
            uint32_t cb = ks*32 + bKh;
            #pragma unroll
            for(int ni = 0; ni < 2; ni++){
                uint32_t bd = bBase[ni] + (cb ^ bXor[ni]);
                LDSM4(bhi[ni], bd);
                LDSM4(bmi[ni], bd + (OT_B_MID - OT_B_HI));
            }
            #pragma unroll
            for(int n8 = 0; n8 < 3; n8++){
                uint32_t bh0 = bhi[n8>>1][(n8&1)*2], bh1 = bhi[n8>>1][(n8&1)*2+1];
                uint32_t bm0 = bmi[n8>>1][(n8&1)*2], bm1 = bmi[n8>>1][(n8&1)*2+1];
                mma16816(acc[n8], ahi, bh0, bh1);
                mma16816(acc[n8], ahi, bm0, bm1);
                mma16816(acc[n8], ami, bh0, bh1);
            }
        }
    }

    const int r0 = m0 + (lid >> 2);
    const int r1 = r0 + 8;
    float* d0 = off + ((size_t)(b*HH + h)*WW + r0)*18;
    float* d1 = off + ((size_t)(b*HH + h)*WW + r1)*18;
    #pragma unroll
    for(int n8 = 0; n8 < 3; n8++){
        int c0 = n8*8 + (lid & 3)*2;
        if(c0 < 18){
            float b0 = __ldg(boff + c0);
            float b1v = __ldg(boff + c0 + 1);
            d0[c0]   = acc[n8][0] + b0;
            d0[c0+1] = acc[n8][1] + b1v;
            d1[c0]   = acc[n8][2] + b0;
            d1[c0+1] = acc[n8][3] + b1v;
        }
    }
}

// ---------------- main DCN v4: tap-pipelined gather + mma.sync bf16 3-split ----------------
// grid = BATCH*HH; M=128 px, N=64 out, K=9x64. Double-buffered A, reg-prefetched B.
// smem byte offsets
#define TB_W_OFF  0          /* float4 wtab[1152] = 18432 */
#define TB_I_OFF  18432      /* uint   itab[1152] = 4608  */
#define A_OFF     23040      /* 2 x (hi 16384 + mid 16384) = 65536 */
#define A_BUF_SZ  32768
#define B_OFF     88576      /* hi 8192 + mid 8192 = 16384 */
#define DCN_SMEM  104960

template<bool NCHW_OUT>
__global__ void __launch_bounds__(256,2) k_dcn(
    const float* __restrict__ xn, const float* __restrict__ off,
    const __nv_bfloat16* __restrict__ wtb, const float* __restrict__ bn,
    float* __restrict__ out)
{
    extern __shared__ char smc[];
    const uint32_t smem_base = smem_to_u32(smc);

    const int b = blockIdx.x >> 7;
    const int h = blockIdx.x & 127;
    const int tid = threadIdx.x;
    const int wid = tid >> 5;
    const int lid = tid & 31;
    const float fh = (float)h;

    float4*   wtab = (float4*)(smc + TB_W_OFF);
    uint32_t* itab = (uint32_t*)(smc + TB_I_OFF);

    // ---------- build compact gather table ----------
    #pragma unroll 1
    for(int e = tid; e < 1152; e += 256){
        int k  = e >> 7;
        int px = e & 127;
        const float* op = off + ((size_t)(b*HH + h)*WW + px)*18 + 2*k;
        float dy = __ldg(op);
        float dx = __ldg(op + 1);
        float py  = fh + (float)(k/3 - 1) + dy;
        float pxx = (float)(px + k%3 - 1) + dx;
        float y0f = floorf(py), x0f = floorf(pxx);
        float wy1 = py - y0f,  wx1 = pxx - x0f;
        float wy0 = 1.f - wy1, wx0 = 1.f - wx1;
        float y1f = y0f + 1.f, x1f = x0f + 1.f;
        bool vy0 = (y0f >= 0.f) && (y0f <= 127.f);
        bool vy1 = (y1f >= 0.f) && (y1f <= 127.f);
        bool vx0 = (x0f >= 0.f) && (x0f <= 127.f);
        bool vx1 = (x1f >= 0.f) && (x1f <= 127.f);
        int yi0 = (int)fminf(fmaxf(y0f,0.f),127.f);
        int yi1 = (int)fminf(fmaxf(y1f,0.f),127.f);
        int xi0 = (int)fminf(fmaxf(x0f,0.f),127.f);
        int xi1 = (int)fminf(fmaxf(x1f,0.f),127.f);
        float w00 = (vy0 && vx0) ? wy0*wx0 : 0.f;
        float w01 = (vy0 && vx1) ? wy0*wx1 : 0.f;
        float w10 = (vy1 && vx0) ? wy1*wx0 : 0.f;
        float w11 = (vy1 && vx1) ? wy1*wx1 : 0.f;
        wtab[e] = make_float4(w00, w01, w10, w11);
        itab[e] = (uint32_t)yi0 | ((uint32_t)xi0 << 8) | ((uint32_t)yi1 << 16) | ((uint32_t)xi1 << 24);
    }
    // stage B(0) (independent of table)
    {
        const uint4* bs = (const uint4*)wtb;
        uint4* bd = (uint4*)(smc + B_OFF);
        #pragma unroll
        for(int j = 0; j < 4; j++) bd[tid + j*256] = __ldg(bs + tid + j*256);
    }

    const char* xq = (const char*)(xn + (size_t)b*HH*WW*CH) + (tid & 15)*16;
    const int q  = tid & 15;
    const int pg = tid >> 4;

    __syncthreads();

    // gather one pixel of one tap into buffer `buf`
    auto gather_px = [&](int k, int px, int buf){
        int e = k*128 + px;
        float4 wv = wtab[e];
        uint32_t ii = itab[e];
        uint32_t ry0 = (ii & 0xffu) << 15;
        uint32_t rx0 = ((ii >> 8) & 0xffu) << 8;
        uint32_t ry1 = ((ii >> 16) & 0xffu) << 15;
        uint32_t rx1 = (ii >> 24) << 8;
        float4 a  = __ldg((const float4*)(xq + ry0 + rx0));
        float4 b2 = __ldg((const float4*)(xq + ry0 + rx1));
        float4 c  = __ldg((const float4*)(xq + ry1 + rx0));
        float4 d  = __ldg((const float4*)(xq + ry1 + rx1));
        float4 r;
        r.x = wv.x*a.x + wv.y*b2.x + wv.z*c.x + wv.w*d.x;
        r.y = wv.x*a.y + wv.y*b2.y + wv.z*c.y + wv.w*d.y;
        r.z = wv.x*a.z + wv.y*b2.z + wv.z*c.z + wv.w*d.z;
        r.w = wv.x*a.w + wv.y*b2.w + wv.z*c.w + wv.w*d.w;
        __nv_bfloat162 h0 = __float22bfloat162_rn(make_float2(r.x, r.y));
        __nv_bfloat162 h1 = __float22bfloat162_rn(make_float2(r.z, r.w));
        float2 f0 = __bfloat1622float2(h0);
        float2 f1 = __bfloat1622float2(h1);
        __nv_bfloat162 m0b = __float22bfloat162_rn(make_float2(r.x - f0.x, r.y - f0.y));
        __nv_bfloat162 m1b = __float22bfloat162_rn(make_float2(r.z - f1.x, r.w - f1.y));
        int sw = SWZ128(px*128 + q*8);
        char* ab = smc + A_OFF + buf*A_BUF_SZ;
        uint2 uh, um;
        uh.x = *(uint32_t*)&h0;  uh.y = *(uint32_t*)&h1;
        um.x = *(uint32_t*)&m0b; um.y = *(uint32_t*)&m1b;
        *(uint2*)(ab + sw)         = uh;
        *(uint2*)(ab + 16384 + sw) = um;
    };

    // prologue: gather A(0) into buf 0
    #pragma unroll 2
    for(int i = 0; i < 8; i++) gather_px(0, pg*8 + i, 0);

    // mma mapping: warp (4 x 2) grid of 32x32 tiles
    const int m0 = (wid >> 1) * 32;
    const int n0 = (wid & 1) * 32;

    uint32_t aRow[2], aXor[2];
    #pragma unroll
    for(int mi = 0; mi < 2; mi++){
        int r = m0 + mi*16 + (lid & 15);
        aRow[mi] = r*128;
        aXor[mi] = (r & 7) << 4;
    }
    const uint32_t aKh = (lid >> 4) * 16;
    uint32_t bBase[2], bXor[2];
    #pragma unroll
    for(int ni = 0; ni < 2; ni++){
        int r = n0 + ni*16 + (lid & 7) + ((lid >> 4) << 3);
        bBase[ni] = smem_base + B_OFF + r*128;
        bXor[ni]  = (r & 7) << 4;
    }
    const uint32_t bKh = ((lid >> 3) & 1) * 16;

    float acc[2][4][4];
    #pragma unroll
    for(int mi = 0; mi < 2; mi++)
        #pragma unroll
        for(int ni = 0; ni < 4; ni++)
            #pragma unroll
            for(int j = 0; j < 4; j++) acc[mi][ni][j] = 0.f;

    __syncthreads();

    int cur = 0;
    #pragma unroll 1
    for(int k = 0; k < 9; k++){
        // prefetch B(k+1) into registers
        uint4 bp0, bp1, bp2, bp3;
        if(k < 8){
            const uint4* bs = (const uint4*)wtb + (k+1)*1024;
            bp0 = __ldg(bs + tid);       bp1 = __ldg(bs + tid + 256);
            bp2 = __ldg(bs + tid + 512); bp3 = __ldg(bs + tid + 768);
        }
        const uint32_t aB = smem_base + A_OFF + cur*A_BUF_SZ;

        #pragma unroll
        for(int ks = 0; ks < 4; ks++){
            uint32_t ahi[2][4], ami[2][4], bhi[2][4], bmi[2][4];
            uint32_t ca = ks*32 + aKh;
            #pragma unroll
            for(int mi = 0; mi < 2; mi++){
                uint32_t ad = aB + aRow[mi] + (ca ^ aXor[mi]);
                LDSM4(ahi[mi], ad);
                LDSM4(ami[mi], ad + 16384);
            }
            uint32_t cb = ks*32 + bKh;
            #pragma unroll
            for(int ni = 0; ni < 2; ni++){
                uint32_t bd = bBase[ni] + (cb ^ bXor[ni]);
                LDSM4(bhi[ni], bd);
                LDSM4(bmi[ni], bd + 8192);
            }
            // gather 2 px of next tap (LDG latency hidden behind the MMAs below)
            if(k < 8){
                gather_px(k+1, pg*8 + ks*2,     cur ^ 1);
                gather_px(k+1, pg*8 + ks*2 + 1, cur ^ 1);
            }
            #pragma unroll
            for(int mi = 0; mi < 2; mi++)
                #pragma unroll
                for(int n8 = 0; n8 < 4; n8++){
                    uint32_t bh0 = bhi[n8>>1][(n8&1)*2], bh1 = bhi[n8>>1][(n8&1)*2+1];
                    uint32_t bm0 = bmi[n8>>1][(n8&1)*2], bm1 = bmi[n8>>1][(n8&1)*2+1];
                    mma16816(acc[mi][n8], ahi[mi], bh0, bh1);
                    mma16816(acc[mi][n8], ahi[mi], bm0, bm1);
                    mma16816(acc[mi][n8], ami[mi], bh0, bh1);
                }
        }
        __syncthreads();
        if(k < 8){
            uint4* bd = (uint4*)(smc + B_OFF);
            bd[tid]       = bp0;
            bd[tid + 256] = bp1;
            bd[tid + 512] = bp2;
            bd[tid + 768] = bp3;
            __syncthreads();
        }
        cur ^= 1;
    }

    // epilogue: BN + ReLU + store
    #pragma unroll
    for(int mi = 0; mi < 2; mi++){
        int r0 = m0 + mi*16 + (lid >> 2);
        int r1 = r0 + 8;
        #pragma unroll
        for(int n8 = 0; n8 < 4; n8++){
            int c0 = n0 + n8*8 + (lid & 3)*2;
            float iv0 = __ldg(bn + c0),      iv1 = __ldg(bn + c0 + 1);
            float bc0 = __ldg(bn + 64 + c0), bc1 = __ldg(bn + 64 + c0 + 1);
            float v00 = fmaxf(acc[mi][n8][0]*iv0 + bc0, 0.f);
            float v01 = fmaxf(acc[mi][n8][1]*iv1 + bc1, 0.f);
            float v10 = fmaxf(acc[mi][n8][2]*iv0 + bc0, 0.f);
            float v11 = fmaxf(acc[mi][n8][3]*iv1 + bc1, 0.f);
            if(NCHW_OUT){
                float* o0 = out + (((size_t)b*CH + c0)*HH + h)*WW;
                float* o1 = out + (((size_t)b*CH + c0+1)*HH + h)*WW;
                o0[r0] = v00; o1[r0] = v01;
                o0[r1] = v10; o1[r1] = v11;
            } else {
                float* base = out + ((size_t)(b*HH + h)*WW)*CH;
                *(float2*)(base + r0*CH + c0) = make_float2(v00, v01);
                *(float2*)(base + r1*CH + c0) = make_float2(v10, v11);
            }
        }
    }
}

// ---------------- launcher ----------------
extern "C" void kernel_launch(void* const* d_in, const int* in_sizes, int n_in,
                              void* d_out, int out_size)
{
    const float* x     = (const float*)d_in[0];
    const float* woff1 = (const float*)d_in[1];
    const float* boff1 = (const float*)d_in[2];
    const float* w1    = (const float*)d_in[3];
    const float* g1    = (const float*)d_in[4];
    const float* be1   = (const float*)d_in[5];
    const float* m1    = (const float*)d_in[6];
    const float* v1    = (const float*)d_in[7];
    const float* woff2 = (const float*)d_in[8];
    const float* boff2 = (const float*)d_in[9];
    const float* w2    = (const float*)d_in[10];
    const float* g2    = (const float*)d_in[11];
    const float* be2   = (const float*)d_in[12];
    const float* m2    = (const float*)d_in[13];
    const float* v2    = (const float*)d_in[14];
    float* out = (float*)d_out;

    float *xn, *y1, *offb, *bn;
    __nv_bfloat16 *wtb1, *wtb2, *wob1, *wob2;
    cudaGetSymbolAddress((void**)&xn,   g_xnhwc);
    cudaGetSymbolAddress((void**)&y1,   g_y1);
    cudaGetSymbolAddress((void**)&offb, g_off);
    cudaGetSymbolAddress((void**)&wtb1, g_wtb1);
    cudaGetSymbolAddress((void**)&wtb2, g_wtb2);
    cudaGetSymbolAddress((void**)&wob1, g_wob1);
    cudaGetSymbolAddress((void**)&wob2, g_wob2);
    cudaGetSymbolAddress((void**)&bn,   g_bn);

    cudaFuncSetAttribute(k_offt,       cudaFuncAttributeMaxDynamicSharedMemorySize, OT_SMEM);
    cudaFuncSetAttribute(k_dcn<false>, cudaFuncAttributeMaxDynamicSharedMemorySize, DCN_SMEM);
    cudaFuncSetAttribute(k_dcn<true>,  cudaFuncAttributeMaxDynamicSharedMemorySize, DCN_SMEM);

    // launch order: k_dcn layer-1 is launch #4 (ncu effective skip = 3)
    k_prep<<<432, 256>>>(w1, w2, woff1, woff2, g1, be1, m1, v1, g2, be2, m2, v2);
    k_nchw2nhwc<<<BATCH*HH, 256>>>(x, xn);
    k_offt<<<BATCH*HH, 256, OT_SMEM>>>(xn, wob1, boff1, offb);
    k_dcn<false><<<BATCH*HH, 256, DCN_SMEM>>>(xn, offb, wtb1, bn, y1);

    k_offt<<<BATCH*HH, 256, OT_SMEM>>>(y1, wob2, boff2, offb);
    k_dcn<true><<<BATCH*HH, 256, DCN_SMEM>>>(y1, offb, wtb2, bn + 128, out);
}

// round 7
// speedup vs baseline: 5.6982x; 1.0593x over previous
#include <cuda_runtime.h>
#include <cuda_bf16.h>
#include <cstdint>

#define HH 128
#define WW 128
#define CH 64
#define BATCH 4
#define EPS 1e-5f

// ---------------- scratch (no mallocs allowed) ----------------
__device__ __align__(16) float g_xnhwc[BATCH*HH*WW*CH];
__device__ __align__(16) float g_y1   [BATCH*HH*WW*CH];
__device__ __align__(16) float g_off  [BATCH*HH*WW*18];   // layout [bh][18][128]
__device__ __align__(1024) __nv_bfloat16 g_wtb1[9*2*64*64];
__device__ __align__(1024) __nv_bfloat16 g_wtb2[9*2*64*64];
__device__ __align__(1024) __nv_bfloat16 g_wob1[9*2*32*64];
__device__ __align__(1024) __nv_bfloat16 g_wob2[9*2*32*64];
__device__ __align__(16) float g_bn[256];

// ---------------- helpers ----------------
static __device__ __forceinline__ uint32_t smem_to_u32(const void* p){
    uint32_t a;
    asm("{ .reg .u64 t; cvta.to.shared.u64 t, %1; cvt.u32.u64 %0, t; }" : "=r"(a) : "l"(p));
    return a;
}
#define SWZ128(o) ((o) ^ (((o) >> 3) & 0x70))

#define LDSM4(r, a) \
    asm volatile("ldmatrix.sync.aligned.m8n8.x4.shared.b16 {%0,%1,%2,%3}, [%4];" \
        : "=r"((r)[0]), "=r"((r)[1]), "=r"((r)[2]), "=r"((r)[3]) : "r"(a))

static __device__ __forceinline__ void mma16816(float* d, const uint32_t* a, uint32_t b0, uint32_t b1){
    asm volatile("mma.sync.aligned.m16n8k16.row.col.f32.bf16.bf16.f32 "
        "{%0,%1,%2,%3},{%4,%5,%6,%7},{%8,%9},{%0,%1,%2,%3};"
        : "+f"(d[0]), "+f"(d[1]), "+f"(d[2]), "+f"(d[3])
        : "r"(a[0]), "r"(a[1]), "r"(a[2]), "r"(a[3]), "r"(b0), "r"(b1));
}

#define CP_ASYNC16(dst, src) \
    asm volatile("cp.async.cg.shared.global [%0], [%1], 16;" :: "r"(dst), "l"(src) : "memory")
#define CP_COMMIT() asm volatile("cp.async.commit_group;" ::: "memory")
#define CP_WAIT0()  asm volatile("cp.async.wait_group 0;" ::: "memory")

// ---------------- prep ----------------
__global__ void k_prep(const float* __restrict__ w1, const float* __restrict__ w2,
                       const float* __restrict__ woff1, const float* __restrict__ woff2,
                       const float* g1, const float* be1, const float* m1, const float* v1,
                       const float* g2, const float* be2, const float* m2, const float* v2)
{
    int i = blockIdx.x*blockDim.x + threadIdx.x;
    if(i < 73728){
        int L   = i / 36864;
        int rem = i % 36864;
        int k = rem >> 12;
        int o = (rem >> 6) & 63;
        int c = rem & 63;
        const float* w = L ? w2 : w1;
        float val = w[(o*64 + c)*9 + k];
        __nv_bfloat16 hb = __float2bfloat16(val);
        float hf = __bfloat162float(hb);
        __nv_bfloat16 mb = __float2bfloat16(val - hf);
        char* dst = (char*)(L ? g_wtb2 : g_wtb1);
        int sw = SWZ128(o*128 + c*2);
        *(__nv_bfloat16*)(dst + k*16384 +        sw) = hb;
        *(__nv_bfloat16*)(dst + k*16384 + 8192 + sw) = mb;
    } else if(i < 110592){
        int j   = i - 73728;
        int L   = j / 18432;
        int rem = j % 18432;
        int k = rem >> 11;
        int o = (rem >> 6) & 31;
        int c = rem & 63;
        const float* w = L ? woff2 : woff1;
        float val = (o < 18) ? w[(o*64 + c)*9 + k] : 0.f;
        __nv_bfloat16 hb = __float2bfloat16(val);
        float hf = __bfloat162float(hb);
        __nv_bfloat16 mb = __float2bfloat16(val - hf);
        char* dst = (char*)(L ? g_wob2 : g_wob1);
        int sw = SWZ128(o*128 + c*2);
        *(__nv_bfloat16*)(dst + k*8192 +        sw) = hb;
        *(__nv_bfloat16*)(dst + k*8192 + 4096 + sw) = mb;
    }
    if(blockIdx.x == 0 && threadIdx.x < 64){
        int t = threadIdx.x;
        float i1 = g1[t] * rsqrtf(v1[t] + EPS);
        g_bn[t]      = i1;
        g_bn[64+t]   = be1[t] - m1[t]*i1;
        float i2 = g2[t] * rsqrtf(v2[t] + EPS);
        g_bn[128+t]  = i2;
        g_bn[192+t]  = be2[t] - m2[t]*i2;
    }
}

// ---------------- NCHW -> NHWC transpose ----------------
__global__ void k_nchw2nhwc(const float* __restrict__ x, float* __restrict__ xn){
    __shared__ float tile[64*129];
    int b = blockIdx.x >> 7;
    int h = blockIdx.x & 127;
    const float* src = x + (b*CH*HH)*WW + h*WW;
    for(int i = threadIdx.x; i < CH*WW; i += blockDim.x){
        int c = i >> 7, w = i & 127;
        tile[c*129 + w] = src[c*HH*WW + w];
    }
    __syncthreads();
    float* dst = xn + ((b*HH + h)*WW)*CH;
    for(int i = threadIdx.x; i < CH*WW; i += blockDim.x){
        int w = i >> 6, c = i & 63;
        dst[w*CH + c] = tile[c*129 + w];
    }
}

// ---------------- offset conv v2: per-ky shared A tile, cp.async B ----------------
// A tile: 130 rows (px -1..128) x 128B, hi + mid. B: 2 slots x (hi 4KB + mid 4KB).
#define OT2_A_HI  0
#define OT2_A_MID 16640
#define OT2_B     33280
#define OT2_SMEM  49664

__global__ void __launch_bounds__(256,3) k_offt(
    const float* __restrict__ xn, const __nv_bfloat16* __restrict__ wob,
    const float* __restrict__ boff, float* __restrict__ off)
{
    extern __shared__ char smc[];
    const uint32_t smem_base = smem_to_u32(smc);

    const int b = blockIdx.x >> 7;
    const int h = blockIdx.x & 127;
    const int tid = threadIdx.x;
    const int wid = tid >> 5;
    const int lid = tid & 31;
    const int m0 = wid * 16;

    const uint32_t aKh = (lid >> 4) * 16;
    const int aR = m0 + (lid & 15);      // A row (pre-shift)
    uint32_t bRow[2], bXor[2];
    #pragma unroll
    for(int ni = 0; ni < 2; ni++){
        int r = ni*16 + (lid & 7) + ((lid >> 4) << 3);
        bRow[ni] = r*128;
        bXor[ni] = (r & 7) << 4;
    }
    const uint32_t bKh = ((lid >> 3) & 1) * 16;

    float acc[3][4];
    #pragma unroll
    for(int n8 = 0; n8 < 3; n8++)
        #pragma unroll
        for(int j = 0; j < 4; j++) acc[n8][j] = 0.f;

    // prologue: prefetch B(0)
    {
        const char* bs = (const char*)wob;
        #pragma unroll
        for(int j = 0; j < 2; j++)
            CP_ASYNC16(smem_base + OT2_B + tid*16 + j*4096, bs + tid*16 + j*4096);
        CP_COMMIT();
    }

    #pragma unroll 1
    for(int ky = 0; ky < 3; ky++){
        __syncthreads();   // everyone done reading previous A tile
        // build A rows for this ky: 130 rows x 16 chunks
        const int hh = h + ky - 1;
        const bool hv = (hh >= 0) && (hh < HH);
        const float* rowp = xn + (size_t)(b*HH + hh)*WW*CH;
        #pragma unroll 1
        for(int idx = tid; idx < 2080; idx += 256){
            int rho = idx >> 4, q = idx & 15;
            int px = rho - 1;
            float4 v = make_float4(0.f,0.f,0.f,0.f);
            if(hv && px >= 0 && px < WW)
                v = __ldg((const float4*)(rowp + px*CH) + q);
            __nv_bfloat162 h0 = __float22bfloat162_rn(make_float2(v.x, v.y));
            __nv_bfloat162 h1 = __float22bfloat162_rn(make_float2(v.z, v.w));
            float2 f0 = __bfloat1622float2(h0);
            float2 f1 = __bfloat1622float2(h1);
            __nv_bfloat162 m0b = __float22bfloat162_rn(make_float2(v.x - f0.x, v.y - f0.y));
            __nv_bfloat162 m1b = __float22bfloat162_rn(make_float2(v.z - f1.x, v.w - f1.y));
            int sw = SWZ128(rho*128 + q*8);
            uint2 uh, um;
            uh.x = *(uint32_t*)&h0;  uh.y = *(uint32_t*)&h1;
            um.x = *(uint32_t*)&m0b; um.y = *(uint32_t*)&m1b;
            *(uint2*)(smc + OT2_A_HI  + sw) = uh;
            *(uint2*)(smc + OT2_A_MID + sw) = um;
        }

        #pragma unroll 1
        for(int kx = 0; kx < 3; kx++){
            int k = ky*3 + kx;
            CP_WAIT0();
            __syncthreads();  // B(k) visible; A tile visible; safe to overwrite slot^1
            if(k < 8){
                const char* bs = (const char*)wob + (k+1)*8192;
                uint32_t bd = smem_base + OT2_B + ((k+1)&1)*8192;
                #pragma unroll
                for(int j = 0; j < 2; j++)
                    CP_ASYNC16(bd + tid*16 + j*4096, bs + tid*16 + j*4096);
                CP_COMMIT();
            }
            const uint32_t slotB = smem_base + OT2_B + (k&1)*8192;
            const int rho = aR + 1 + kx - 1;   // global row aR + kx-1, +1 tile offset
            const uint32_t aAddrBase = smem_base + OT2_A_HI + rho*128;
            const uint32_t aXor = (rho & 7) << 4;

            #pragma unroll
            for(int ks = 0; ks < 4; ks++){
                uint32_t ahi[4], ami[4], bhi[2][4], bmi[2][4];
                uint32_t ad = aAddrBase + ((ks*32 + aKh) ^ aXor);
                LDSM4(ahi, ad);
                LDSM4(ami, ad + (OT2_A_MID - OT2_A_HI));
                uint32_t cb = ks*32 + bKh;
                #pragma unroll
                for(int ni = 0; ni < 2; ni++){
                    uint32_t bd = slotB + bRow[ni] + (cb ^ bXor[ni]);
                    LDSM4(bhi[ni], bd);
                    LDSM4(bmi[ni], bd + 4096);
                }
                #pragma unroll
                for(int n8 = 0; n8 < 3; n8++){
                    uint32_t bh0 = bhi[n8>>1][(n8&1)*2], bh1 = bhi[n8>>1][(n8&1)*2+1];
                    uint32_t bm0 = bmi[n8>>1][(n8&1)*2], bm1 = bmi[n8>>1][(n8&1)*2+1];
                    mma16816(acc[n8], ahi, bh0, bh1);
                    mma16816(acc[n8], ahi, bm0, bm1);
                    mma16816(acc[n8], ami, bh0, bh1);
                }
            }
        }
    }

    // epilogue: bias + store to off[bh][c][px]
    const int r0 = m0 + (lid >> 2);
    const int r1 = r0 + 8;
    float* base = off + (size_t)(b*HH + h)*2304;
    #pragma unroll
    for(int n8 = 0; n8 < 3; n8++){
        int c0 = n8*8 + (lid & 3)*2;
        if(c0 < 18){
            float b0 = __ldg(boff + c0);
            float b1v = __ldg(boff + c0 + 1);
            base[c0*128 + r0]     = acc[n8][0] + b0;
            base[(c0+1)*128 + r0] = acc[n8][1] + b1v;
            base[c0*128 + r1]     = acc[n8][2] + b0;
            base[(c0+1)*128 + r1] = acc[n8][3] + b1v;
        }
    }
}

// ---------------- main DCN v5: compact table, cp.async B dbl-buf, 1 sync/tap ----------------
#define TB_W_OFF  0          /* float2 wtab2[1152] = 9216 */
#define TB_I_OFF  9216       /* uint   itab [1152] = 4608 */
#define A_OFF     13824      /* 2 x (hi 16384 + mid 16384) */
#define A_BUF_SZ  32768
#define B_OFF     79360      /* 2 x (hi 8192 + mid 8192) */
#define DCN_SMEM  112128

template<bool NCHW_OUT>
__global__ void __launch_bounds__(256,2) k_dcn(
    const float* __restrict__ xn, const float* __restrict__ off,
    const __nv_bfloat16* __restrict__ wtb, const float* __restrict__ bn,
    float* __restrict__ out)
{
    extern __shared__ char smc[];
    const uint32_t smem_base = smem_to_u32(smc);

    const int b = blockIdx.x >> 7;
    const int h = blockIdx.x & 127;
    const int tid = threadIdx.x;
    const int wid = tid >> 5;
    const int lid = tid & 31;
    const float fh = (float)h;

    float2*   wtab2 = (float2*)(smc + TB_W_OFF);
    uint32_t* itab  = (uint32_t*)(smc + TB_I_OFF);

    // prefetch B(0)
    {
        const char* bs = (const char*)wtb;
        #pragma unroll
        for(int j = 0; j < 4; j++)
            CP_ASYNC16(smem_base + B_OFF + tid*16 + j*4096, bs + tid*16 + j*4096);
        CP_COMMIT();
    }

    // ---------- build compact gather table ----------
    {
        const float* offb2 = off + (size_t)(b*HH + h)*2304;
        #pragma unroll 1
        for(int e = tid; e < 1152; e += 256){
            int k  = e >> 7;
            int px = e & 127;
            float dy = __ldg(offb2 + (2*k)*128 + px);
            float dx = __ldg(offb2 + (2*k+1)*128 + px);
            float py  = fh + (float)(k/3 - 1) + dy;
            float pxx = (float)(px + k%3 - 1) + dx;
            float y0f = floorf(py), x0f = floorf(pxx);
            float wy1 = py - y0f,  wx1 = pxx - x0f;
            bool vy0 = (y0f >= 0.f)  && (y0f <= 127.f);
            bool vy1 = (y0f >= -1.f) && (y0f <= 126.f);
            bool vx0 = (x0f >= 0.f)  && (x0f <= 127.f);
            bool vx1 = (x0f >= -1.f) && (x0f <= 126.f);
            uint32_t yi0 = (uint32_t)(int)fminf(fmaxf(y0f,      0.f),127.f);
            uint32_t yi1 = (uint32_t)(int)fminf(fmaxf(y0f + 1.f,0.f),127.f);
            uint32_t xi0 = (uint32_t)(int)fminf(fmaxf(x0f,      0.f),127.f);
            uint32_t xi1 = (uint32_t)(int)fminf(fmaxf(x0f + 1.f,0.f),127.f);
            wtab2[e] = make_float2(wy1, wx1);
            itab[e]  = yi0 | (yi1 << 7) | (xi0 << 14) | (xi1 << 21)
                     | (vy0 ? 1u<<28 : 0u) | (vy1 ? 1u<<29 : 0u)
                     | (vx0 ? 1u<<30 : 0u) | (vx1 ? 1u<<31 : 0u);
        }
    }

    const char* xq = (const char*)(xn + (size_t)b*HH*WW*CH) + (tid & 15)*16;
    const int q  = tid & 15;
    const int pg = tid >> 4;

    __syncthreads();  // table visible

    auto gather_px = [&](int k, int px, int buf){
        int e = k*128 + px;
        float2 t = wtab2[e];
        uint32_t ii = itab[e];
        float ay0 = (ii & (1u<<28)) ? (1.f - t.x) : 0.f;
        float ay1 = (ii & (1u<<29)) ? t.x : 0.f;
        float ax0 = (ii & (1u<<30)) ? (1.f - t.y) : 0.f;
        float ax1 = (ii & (1u<<31)) ? t.y : 0.f;
        uint32_t ry0 = (ii & 0x7fu) << 15;
        uint32_t ry1 = ((ii >> 7) & 0x7fu) << 15;
        uint32_t rx0 = ((ii >> 14) & 0x7fu) << 8;
        uint32_t rx1 = ((ii >> 21) & 0x7fu) << 8;
        float w00 = ay0*ax0, w01 = ay0*ax1, w10 = ay1*ax0, w11 = ay1*ax1;
        float4 a  = __ldg((const float4*)(xq + ry0 + rx0));
        float4 b2 = __ldg((const float4*)(xq + ry0 + rx1));
        float4 c  = __ldg((const float4*)(xq + ry1 + rx0));
        float4 d  = __ldg((const float4*)(xq + ry1 + rx1));
        float4 r;
        r.x = w00*a.x + w01*b2.x + w10*c.x + w11*d.x;
        r.y = w00*a.y + w01*b2.y + w10*c.y + w11*d.y;
        r.z = w00*a.z + w01*b2.z + w10*c.z + w11*d.z;
        r.w = w00*a.w + w01*b2.w + w10*c.w + w11*d.w;
        __nv_bfloat162 h0 = __float22bfloat162_rn(make_float2(r.x, r.y));
        __nv_bfloat162 h1 = __float22bfloat162_rn(make_float2(r.z, r.w));
        float2 f0 = __bfloat1622float2(h0);
        float2 f1 = __bfloat1622float2(h1);
        __nv_bfloat162 m0b = __float22bfloat162_rn(make_float2(r.x - f0.x, r.y - f0.y));
        __nv_bfloat162 m1b = __float22bfloat162_rn(make_float2(r.z - f1.x, r.w - f1.y));
        int sw = SWZ128(px*128 + q*8);
        char* ab = smc + A_OFF + buf*A_BUF_SZ;
        uint2 uh, um;
        uh.x = *(uint32_t*)&h0;  uh.y = *(uint32_t*)&h1;
        um.x = *(uint32_t*)&m0b; um.y = *(uint32_t*)&m1b;
        *(uint2*)(ab + sw)         = uh;
        *(uint2*)(ab + 16384 + sw) = um;
    };

    // prologue gather A(0)
    #pragma unroll 2
    for(int i = 0; i < 8; i++) gather_px(0, pg*8 + i, 0);

    // mma mapping: warp (4 x 2) grid of 32x32 tiles
    const int m0 = (wid >> 1) * 32;
    const int n0 = (wid & 1) * 32;

    uint32_t aRow[2], aXor[2];
    #pragma unroll
    for(int mi = 0; mi < 2; mi++){
        int r = m0 + mi*16 + (lid & 15);
        aRow[mi] = r*128;
        aXor[mi] = (r & 7) << 4;
    }
    const uint32_t aKh = (lid >> 4) * 16;
    uint32_t bRow[2], bXor[2];
    #pragma unroll
    for(int ni = 0; ni < 2; ni++){
        int r = n0 + ni*16 + (lid & 7) + ((lid >> 4) << 3);
        bRow[ni] = r*128;
        bXor[ni] = (r & 7) << 4;
    }
    const uint32_t bKh = ((lid >> 3) & 1) * 16;

    float acc[2][4][4];
    #pragma unroll
    for(int mi = 0; mi < 2; mi++)
        #pragma unroll
        for(int ni = 0; ni < 4; ni++)
            #pragma unroll
            for(int j = 0; j < 4; j++) acc[mi][ni][j] = 0.f;

    int cur = 0;
    #pragma unroll 1
    for(int k = 0; k < 9; k++){
        CP_WAIT0();
        __syncthreads();  // B(k) + A(k) visible; safe to overwrite B slot^1
        if(k < 8){
            const char* bs = (const char*)wtb + (k+1)*16384;
            uint32_t bd = smem_base + B_OFF + ((k+1)&1)*16384;
            #pragma unroll
            for(int j = 0; j < 4; j++)
                CP_ASYNC16(bd + tid*16 + j*4096, bs + tid*16 + j*4096);
            CP_COMMIT();
        }
        const uint32_t aB    = smem_base + A_OFF + cur*A_BUF_SZ;
        const uint32_t slotB = smem_base + B_OFF + (k&1)*16384;

        #pragma unroll
        for(int ks = 0; ks < 4; ks++){
            uint32_t ahi[2][4], ami[2][4], bhi[2][4], bmi[2][4];
            uint32_t ca = ks*32 + aKh;
            #pragma unroll
            for(int mi = 0; mi < 2; mi++){
                uint32_t ad = aB + aRow[mi] + (ca ^ aXor[mi]);
                LDSM4(ahi[mi], ad);
                LDSM4(ami[mi], ad + 16384);
            }
            uint32_t cb = ks*32 + bKh;
            #pragma unroll
            for(int ni = 0; ni < 2; ni++){
                uint32_t bd = slotB + bRow[ni] + (cb ^ bXor[ni]);
                LDSM4(bhi[ni], bd);
                LDSM4(bmi[ni], bd + 8192);
            }
            if(k < 8){
                gather_px(k+1, pg*8 + ks*2,     cur ^ 1);
                gather_px(k+1, pg*8 + ks*2 + 1, cur ^ 1);
            }
            #pragma unroll
            for(int mi = 0; mi < 2; mi++)
                #pragma unroll
                for(int n8 = 0; n8 < 4; n8++){
                    uint32_t bh0 = bhi[n8>>1][(n8&1)*2], bh1 = bhi[n8>>1][(n8&1)*2+1];
                    uint32_t bm0 = bmi[n8>>1][(n8&1)*2], bm1 = bmi[n8>>1][(n8&1)*2+1];
                    mma16816(acc[mi][n8], ahi[mi], bh0, bh1);
                    mma16816(acc[mi][n8], ahi[mi], bm0, bm1);
                    mma16816(acc[mi][n8], ami[mi], bh0, bh1);
                }
        }
        cur ^= 1;
    }

    // epilogue: BN + ReLU + store
    #pragma unroll
    for(int mi = 0; mi < 2; mi++){
        int r0 = m0 + mi*16 + (lid >> 2);
        int r1 = r0 + 8;
        #pragma unroll
        for(int n8 = 0; n8 < 4; n8++){
            int c0 = n0 + n8*8 + (lid & 3)*2;
            float iv0 = __ldg(bn + c0),      iv1 = __ldg(bn + c0 + 1);
            float bc0 = __ldg(bn + 64 + c0), bc1 = __ldg(bn + 64 + c0 + 1);
            float v00 = fmaxf(acc[mi][n8][0]*iv0 + bc0, 0.f);
            float v01 = fmaxf(acc[mi][n8][1]*iv1 + bc1, 0.f);
            float v10 = fmaxf(acc[mi][n8][2]*iv0 + bc0, 0.f);
            float v11 = fmaxf(acc[mi][n8][3]*iv1 + bc1, 0.f);
            if(NCHW_OUT){
                float* o0 = out + (((size_t)b*CH + c0)*HH + h)*WW;
                float* o1 = out + (((size_t)b*CH + c0+1)*HH + h)*WW;
                o0[r0] = v00; o1[r0] = v01;
                o0[r1] = v10; o1[r1] = v11;
            } else {
                float* base = out + ((size_t)(b*HH + h)*WW)*CH;
                *(float2*)(base + r0*CH + c0) = make_float2(v00, v01);
                *(float2*)(base + r1*CH + c0) = make_float2(v10, v11);
            }
        }
    }
}

// ---------------- launcher ----------------
extern "C" void kernel_launch(void* const* d_in, const int* in_sizes, int n_in,
                              void* d_out, int out_size)
{
    const float* x     = (const float*)d_in[0];
    const float* woff1 = (const float*)d_in[1];
    const float* boff1 = (const float*)d_in[2];
    const float* w1    = (const float*)d_in[3];
    const float* g1    = (const float*)d_in[4];
    const float* be1   = (const float*)d_in[5];
    const float* m1    = (const float*)d_in[6];
    const float* v1    = (const float*)d_in[7];
    const float* woff2 = (const float*)d_in[8];
    const float* boff2 = (const float*)d_in[9];
    const float* w2    = (const float*)d_in[10];
    const float* g2    = (const float*)d_in[11];
    const float* be2   = (const float*)d_in[12];
    const float* m2    = (const float*)d_in[13];
    const float* v2    = (const float*)d_in[14];
    float* out = (float*)d_out;

    float *xn, *y1, *offb, *bn;
    __nv_bfloat16 *wtb1, *wtb2, *wob1, *wob2;
    cudaGetSymbolAddress((void**)&xn,   g_xnhwc);
    cudaGetSymbolAddress((void**)&y1,   g_y1);
    cudaGetSymbolAddress((void**)&offb, g_off);
    cudaGetSymbolAddress((void**)&wtb1, g_wtb1);
    cudaGetSymbolAddress((void**)&wtb2, g_wtb2);
    cudaGetSymbolAddress((void**)&wob1, g_wob1);
    cudaGetSymbolAddress((void**)&wob2, g_wob2);
    cudaGetSymbolAddress((void**)&bn,   g_bn);

    cudaFuncSetAttribute(k_offt,       cudaFuncAttributeMaxDynamicSharedMemorySize, OT2_SMEM);
    cudaFuncSetAttribute(k_dcn<false>, cudaFuncAttributeMaxDynamicSharedMemorySize, DCN_SMEM);
    cudaFuncSetAttribute(k_dcn<true>,  cudaFuncAttributeMaxDynamicSharedMemorySize, DCN_SMEM);

    // launch order: k_dcn layer-1 is launch #4 (ncu effective skip = 3)
    k_prep<<<432, 256>>>(w1, w2, woff1, woff2, g1, be1, m1, v1, g2, be2, m2, v2);
    k_nchw2nhwc<<<BATCH*HH, 256>>>(x, xn);
    k_offt<<<BATCH*HH, 256, OT2_SMEM>>>(xn, wob1, boff1, offb);
    k_dcn<false><<<BATCH*HH, 256, DCN_SMEM>>>(xn, offb, wtb1, bn, y1);

    k_offt<<<BATCH*HH, 256, OT2_SMEM>>>(y1, wob2, boff2, offb);
    k_dcn<true><<<BATCH*HH, 256, DCN_SMEM>>>(y1, offb, wtb2, bn + 128, out);
}

// round 8
// speedup vs baseline: 5.7044x; 1.0011x over previous
#include <cuda_runtime.h>
#include <cuda_bf16.h>
#include <cstdint>

#define HH 128
#define WW 128
#define CH 64
#define BATCH 4
#define EPS 1e-5f

// ---------------- scratch (no mallocs allowed) ----------------
__device__ __align__(16) float g_xnhwc[BATCH*HH*WW*CH];
__device__ __align__(16) float g_y1   [BATCH*HH*WW*CH];
__device__ __align__(16) float g_off  [BATCH*HH*WW*18];   // layout [bh][18][128]
__device__ __align__(1024) __nv_bfloat16 g_wtb1[9*2*64*64];
__device__ __align__(1024) __nv_bfloat16 g_wtb2[9*2*64*64];
__device__ __align__(1024) __nv_bfloat16 g_wob1[9*2*32*64];
__device__ __align__(1024) __nv_bfloat16 g_wob2[9*2*32*64];
__device__ __align__(16) float g_bn[256];

// ---------------- helpers ----------------
static __device__ __forceinline__ uint32_t smem_to_u32(const void* p){
    uint32_t a;
    asm("{ .reg .u64 t; cvta.to.shared.u64 t, %1; cvt.u32.u64 %0, t; }" : "=r"(a) : "l"(p));
    return a;
}
#define SWZ128(o) ((o) ^ (((o) >> 3) & 0x70))

#define LDSM4(r, a) \
    asm volatile("ldmatrix.sync.aligned.m8n8.x4.shared.b16 {%0,%1,%2,%3}, [%4];" \
        : "=r"((r)[0]), "=r"((r)[1]), "=r"((r)[2]), "=r"((r)[3]) : "r"(a))

static __device__ __forceinline__ void mma16816(float* d, const uint32_t* a, uint32_t b0, uint32_t b1){
    asm volatile("mma.sync.aligned.m16n8k16.row.col.f32.bf16.bf16.f32 "
        "{%0,%1,%2,%3},{%4,%5,%6,%7},{%8,%9},{%0,%1,%2,%3};"
        : "+f"(d[0]), "+f"(d[1]), "+f"(d[2]), "+f"(d[3])
        : "r"(a[0]), "r"(a[1]), "r"(a[2]), "r"(a[3]), "r"(b0), "r"(b1));
}

#define CP_ASYNC16(dst, src) \
    asm volatile("cp.async.cg.shared.global [%0], [%1], 16;" :: "r"(dst), "l"(src) : "memory")
#define CP_COMMIT() asm volatile("cp.async.commit_group;" ::: "memory")
#define CP_WAIT0()  asm volatile("cp.async.wait_group 0;" ::: "memory")

// ---------------- prep ----------------
__global__ void k_prep(const float* __restrict__ w1, const float* __restrict__ w2,
                       const float* __restrict__ woff1, const float* __restrict__ woff2,
                       const float* g1, const float* be1, const float* m1, const float* v1,
                       const float* g2, const float* be2, const float* m2, const float* v2)
{
    int i = blockIdx.x*blockDim.x + threadIdx.x;
    if(i < 73728){
        int L   = i / 36864;
        int rem = i % 36864;
        int k = rem >> 12;
        int o = (rem >> 6) & 63;
        int c = rem & 63;
        const float* w = L ? w2 : w1;
        float val = w[(o*64 + c)*9 + k];
        __nv_bfloat16 hb = __float2bfloat16(val);
        float hf = __bfloat162float(hb);
        __nv_bfloat16 mb = __float2bfloat16(val - hf);
        char* dst = (char*)(L ? g_wtb2 : g_wtb1);
        int sw = SWZ128(o*128 + c*2);
        *(__nv_bfloat16*)(dst + k*16384 +        sw) = hb;
        *(__nv_bfloat16*)(dst + k*16384 + 8192 + sw) = mb;
    } else if(i < 110592){
        int j   = i - 73728;
        int L   = j / 18432;
        int rem = j % 18432;
        int k = rem >> 11;
        int o = (rem >> 6) & 31;
        int c = rem & 63;
        const float* w = L ? woff2 : woff1;
        float val = (o < 18) ? w[(o*64 + c)*9 + k] : 0.f;
        __nv_bfloat16 hb = __float2bfloat16(val);
        float hf = __bfloat162float(hb);
        __nv_bfloat16 mb = __float2bfloat16(val - hf);
        char* dst = (char*)(L ? g_wob2 : g_wob1);
        int sw = SWZ128(o*128 + c*2);
        *(__nv_bfloat16*)(dst + k*8192 +        sw) = hb;
        *(__nv_bfloat16*)(dst + k*8192 + 4096 + sw) = mb;
    }
    if(blockIdx.x == 0 && threadIdx.x < 64){
        int t = threadIdx.x;
        float i1 = g1[t] * rsqrtf(v1[t] + EPS);
        g_bn[t]      = i1;
        g_bn[64+t]   = be1[t] - m1[t]*i1;
        float i2 = g2[t] * rsqrtf(v2[t] + EPS);
        g_bn[128+t]  = i2;
        g_bn[192+t]  = be2[t] - m2[t]*i2;
    }
}

// ---------------- NCHW -> NHWC transpose ----------------
__global__ void k_nchw2nhwc(const float* __restrict__ x, float* __restrict__ xn){
    __shared__ float tile[64*129];
    int b = blockIdx.x >> 7;
    int h = blockIdx.x & 127;
    const float* src = x + (b*CH*HH)*WW + h*WW;
    for(int i = threadIdx.x; i < CH*WW; i += blockDim.x){
        int c = i >> 7, w = i & 127;
        tile[c*129 + w] = src[c*HH*WW + w];
    }
    __syncthreads();
    float* dst = xn + ((b*HH + h)*WW)*CH;
    for(int i = threadIdx.x; i < CH*WW; i += blockDim.x){
        int w = i >> 6, c = i & 63;
        dst[w*CH + c] = tile[c*129 + w];
    }
}

// ---------------- offset conv v2: per-ky shared A tile, cp.async B ----------------
#define OT2_A_HI  0
#define OT2_A_MID 16640
#define OT2_B     33280
#define OT2_SMEM  49664

__global__ void __launch_bounds__(256,3) k_offt(
    const float* __restrict__ xn, const __nv_bfloat16* __restrict__ wob,
    const float* __restrict__ boff, float* __restrict__ off)
{
    extern __shared__ char smc[];
    const uint32_t smem_base = smem_to_u32(smc);

    const int b = blockIdx.x >> 7;
    const int h = blockIdx.x & 127;
    const int tid = threadIdx.x;
    const int wid = tid >> 5;
    const int lid = tid & 31;
    const int m0 = wid * 16;

    const uint32_t aKh = (lid >> 4) * 16;
    const int aR = m0 + (lid & 15);
    uint32_t bRow[2], bXor[2];
    #pragma unroll
    for(int ni = 0; ni < 2; ni++){
        int r = ni*16 + (lid & 7) + ((lid >> 4) << 3);
        bRow[ni] = r*128;
        bXor[ni] = (r & 7) << 4;
    }
    const uint32_t bKh = ((lid >> 3) & 1) * 16;

    float acc[3][4];
    #pragma unroll
    for(int n8 = 0; n8 < 3; n8++)
        #pragma unroll
        for(int j = 0; j < 4; j++) acc[n8][j] = 0.f;

    {
        const char* bs = (const char*)wob;
        #pragma unroll
        for(int j = 0; j < 2; j++)
            CP_ASYNC16(smem_base + OT2_B + tid*16 + j*4096, bs + tid*16 + j*4096);
        CP_COMMIT();
    }

    #pragma unroll 1
    for(int ky = 0; ky < 3; ky++){
        __syncthreads();
        const int hh = h + ky - 1;
        const bool hv = (hh >= 0) && (hh < HH);
        const float* rowp = xn + (size_t)(b*HH + hh)*WW*CH;
        #pragma unroll 1
        for(int idx = tid; idx < 2080; idx += 256){
            int rho = idx >> 4, q = idx & 15;
            int px = rho - 1;
            float4 v = make_float4(0.f,0.f,0.f,0.f);
            if(hv && px >= 0 && px < WW)
                v = __ldg((const float4*)(rowp + px*CH) + q);
            __nv_bfloat162 h0 = __float22bfloat162_rn(make_float2(v.x, v.y));
            __nv_bfloat162 h1 = __float22bfloat162_rn(make_float2(v.z, v.w));
            float2 f0 = __bfloat1622float2(h0);
            float2 f1 = __bfloat1622float2(h1);
            __nv_bfloat162 m0b = __float22bfloat162_rn(make_float2(v.x - f0.x, v.y - f0.y));
            __nv_bfloat162 m1b = __float22bfloat162_rn(make_float2(v.z - f1.x, v.w - f1.y));
            int sw = SWZ128(rho*128 + q*8);
            uint2 uh, um;
            uh.x = *(uint32_t*)&h0;  uh.y = *(uint32_t*)&h1;
            um.x = *(uint32_t*)&m0b; um.y = *(uint32_t*)&m1b;
            *(uint2*)(smc + OT2_A_HI  + sw) = uh;
            *(uint2*)(smc + OT2_A_MID + sw) = um;
        }

        #pragma unroll 1
        for(int kx = 0; kx < 3; kx++){
            int k = ky*3 + kx;
            CP_WAIT0();
            __syncthreads();
            if(k < 8){
                const char* bs = (const char*)wob + (k+1)*8192;
                uint32_t bd = smem_base + OT2_B + ((k+1)&1)*8192;
                #pragma unroll
                for(int j = 0; j < 2; j++)
                    CP_ASYNC16(bd + tid*16 + j*4096, bs + tid*16 + j*4096);
                CP_COMMIT();
            }
            const uint32_t slotB = smem_base + OT2_B + (k&1)*8192;
            const int rho = aR + 1 + kx - 1;
            const uint32_t aAddrBase = smem_base + OT2_A_HI + rho*128;
            const uint32_t aXor = (rho & 7) << 4;

            #pragma unroll
            for(int ks = 0; ks < 4; ks++){
                uint32_t ahi[4], ami[4], bhi[2][4], bmi[2][4];
                uint32_t ad = aAddrBase + ((ks*32 + aKh) ^ aXor);
                LDSM4(ahi, ad);
                LDSM4(ami, ad + (OT2_A_MID - OT2_A_HI));
                uint32_t cb = ks*32 + bKh;
                #pragma unroll
                for(int ni = 0; ni < 2; ni++){
                    uint32_t bd = slotB + bRow[ni] + (cb ^ bXor[ni]);
                    LDSM4(bhi[ni], bd);
                    LDSM4(bmi[ni], bd + 4096);
                }
                #pragma unroll
                for(int n8 = 0; n8 < 3; n8++){
                    uint32_t bh0 = bhi[n8>>1][(n8&1)*2], bh1 = bhi[n8>>1][(n8&1)*2+1];
                    uint32_t bm0 = bmi[n8>>1][(n8&1)*2], bm1 = bmi[n8>>1][(n8&1)*2+1];
                    mma16816(acc[n8], ahi, bh0, bh1);
                    mma16816(acc[n8], ahi, bm0, bm1);
                    mma16816(acc[n8], ami, bh0, bh1);
                }
            }
        }
    }

    const int r0 = m0 + (lid >> 2);
    const int r1 = r0 + 8;
    float* base = off + (size_t)(b*HH + h)*2304;
    #pragma unroll
    for(int n8 = 0; n8 < 3; n8++){
        int c0 = n8*8 + (lid & 3)*2;
        if(c0 < 18){
            float b0 = __ldg(boff + c0);
            float b1v = __ldg(boff + c0 + 1);
            base[c0*128 + r0]     = acc[n8][0] + b0;
            base[(c0+1)*128 + r0] = acc[n8][1] + b1v;
            base[c0*128 + r1]     = acc[n8][2] + b0;
            base[(c0+1)*128 + r1] = acc[n8][3] + b1v;
        }
    }
}

// ---------------- main DCN v6: 3 CTAs/SM, A single-buffer, quantized table ----------------
#define TB_OFF    0          /* uint2 tab[1152] = 9216 */
#define A_OFF     9216       /* hi 16384 + mid 16384 */
#define B_OFF     41984      /* 2 x (hi 8192 + mid 8192) */
#define DCN_SMEM  74752

template<bool NCHW_OUT>
__global__ void __launch_bounds__(256,3) k_dcn(
    const float* __restrict__ xn, const float* __restrict__ off,
    const __nv_bfloat16* __restrict__ wtb, const float* __restrict__ bn,
    float* __restrict__ out)
{
    extern __shared__ char smc[];
    const uint32_t smem_base = smem_to_u32(smc);

    const int b = blockIdx.x >> 7;
    const int h = blockIdx.x & 127;
    const int tid = threadIdx.x;
    const int wid = tid >> 5;
    const int lid = tid & 31;
    const float fh = (float)h;

    // prefetch B(0)
    {
        const char* bs = (const char*)wtb;
        #pragma unroll
        for(int j = 0; j < 4; j++)
            CP_ASYNC16(smem_base + B_OFF + tid*16 + j*4096, bs + tid*16 + j*4096);
        CP_COMMIT();
    }

    // ---------- build quantized gather table (8B/entry) ----------
    {
        uint2* tab = (uint2*)(smc + TB_OFF);
        const float* offb2 = off + (size_t)(b*HH + h)*2304;
        #pragma unroll 1
        for(int e = tid; e < 1152; e += 256){
            int k  = e >> 7;
            int px = e & 127;
            float dy = __ldg(offb2 + (2*k)*128 + px);
            float dx = __ldg(offb2 + (2*k+1)*128 + px);
            float py  = fh + (float)(k/3 - 1) + dy;
            float pxx = (float)(px + k%3 - 1) + dx;
            float y0f = floorf(py), x0f = floorf(pxx);
            float wy1 = py - y0f,  wx1 = pxx - x0f;
            bool vy0 = (y0f >= 0.f)  && (y0f <= 127.f);
            bool vy1 = (y0f >= -1.f) && (y0f <= 126.f);
            bool vx0 = (x0f >= 0.f)  && (x0f <= 127.f);
            bool vx1 = (x0f >= -1.f) && (x0f <= 126.f);
            uint32_t yi0 = (uint32_t)(int)fminf(fmaxf(y0f,      0.f),127.f);
            uint32_t yi1 = (uint32_t)(int)fminf(fmaxf(y0f + 1.f,0.f),127.f);
            uint32_t xi0 = (uint32_t)(int)fminf(fmaxf(x0f,      0.f),127.f);
            uint32_t xi1 = (uint32_t)(int)fminf(fmaxf(x0f + 1.f,0.f),127.f);
            uint32_t wyq = (uint32_t)(wy1 * 65535.f);
            uint32_t wxq = (uint32_t)(wx1 * 65535.f);
            uint2 te;
            te.x = wyq | (wxq << 16);
            te.y = yi0 | (yi1 << 7) | (xi0 << 14) | (xi1 << 21)
                 | (vy0 ? 1u<<28 : 0u) | (vy1 ? 1u<<29 : 0u)
                 | (vx0 ? 1u<<30 : 0u) | (vx1 ? 1u<<31 : 0u);
            tab[e] = te;
        }
    }

    const char* xq = (const char*)(xn + (size_t)b*HH*WW*CH) + (tid & 15)*16;
    const int q  = tid & 15;
    const int pg = tid >> 4;

    // mma mapping: warp (4 x 2) grid of 32x32 tiles
    const int m0 = (wid >> 1) * 32;
    const int n0 = (wid & 1) * 32;

    uint32_t aRow[2], aXor[2];
    #pragma unroll
    for(int mi = 0; mi < 2; mi++){
        int r = m0 + mi*16 + (lid & 15);
        aRow[mi] = r*128;
        aXor[mi] = (r & 7) << 4;
    }
    const uint32_t aKh = (lid >> 4) * 16;
    uint32_t bRow[2], bXor[2];
    #pragma unroll
    for(int ni = 0; ni < 2; ni++){
        int r = n0 + ni*16 + (lid & 7) + ((lid >> 4) << 3);
        bRow[ni] = r*128;
        bXor[ni] = (r & 7) << 4;
    }
    const uint32_t bKh = ((lid >> 3) & 1) * 16;

    float acc[2][4][4];
    #pragma unroll
    for(int mi = 0; mi < 2; mi++)
        #pragma unroll
        for(int ni = 0; ni < 4; ni++)
            #pragma unroll
            for(int j = 0; j < 4; j++) acc[mi][ni][j] = 0.f;

    __syncthreads();  // table visible

    const uint2* tab = (const uint2*)(smc + TB_OFF);

    #pragma unroll 1
    for(int k = 0; k < 9; k++){
        // gather A(k) into the (single) A buffer
        #pragma unroll 2
        for(int i = 0; i < 8; i++){
            int px = pg*8 + i;
            uint2 te = tab[k*128 + px];
            float wy1 = (float)(te.x & 0xffffu) * (1.f/65535.f);
            float wx1 = (float)(te.x >> 16)     * (1.f/65535.f);
            uint32_t ii = te.y;
            float ay0 = (ii & (1u<<28)) ? (1.f - wy1) : 0.f;
            float ay1 = (ii & (1u<<29)) ? wy1 : 0.f;
            float ax0 = (ii & (1u<<30)) ? (1.f - wx1) : 0.f;
            float ax1 = (ii & (1u<<31)) ? wx1 : 0.f;
            uint32_t ry0 = (ii & 0x7fu) << 15;
            uint32_t ry1 = ((ii >> 7) & 0x7fu) << 15;
            uint32_t rx0 = ((ii >> 14) & 0x7fu) << 8;
            uint32_t rx1 = ((ii >> 21) & 0x7fu) << 8;
            float w00 = ay0*ax0, w01 = ay0*ax1, w10 = ay1*ax0, w11 = ay1*ax1;
            float4 a  = __ldg((const float4*)(xq + ry0 + rx0));
            float4 b2 = __ldg((const float4*)(xq + ry0 + rx1));
            float4 c  = __ldg((const float4*)(xq + ry1 + rx0));
            float4 d  = __ldg((const float4*)(xq + ry1 + rx1));
            float4 r;
            r.x = w00*a.x + w01*b2.x + w10*c.x + w11*d.x;
            r.y = w00*a.y + w01*b2.y + w10*c.y + w11*d.y;
            r.z = w00*a.z + w01*b2.z + w10*c.z + w11*d.z;
            r.w = w00*a.w + w01*b2.w + w10*c.w + w11*d.w;
            __nv_bfloat162 h0 = __float22bfloat162_rn(make_float2(r.x, r.y));
            __nv_bfloat162 h1 = __float22bfloat162_rn(make_float2(r.z, r.w));
            float2 f0 = __bfloat1622float2(h0);
            float2 f1 = __bfloat1622float2(h1);
            __nv_bfloat162 m0b = __float22bfloat162_rn(make_float2(r.x - f0.x, r.y - f0.y));
            __nv_bfloat162 m1b = __float22bfloat162_rn(make_float2(r.z - f1.x, r.w - f1.y));
            int sw = SWZ128(px*128 + q*8);
            uint2 uh, um;
            uh.x = *(uint32_t*)&h0;  uh.y = *(uint32_t*)&h1;
            um.x = *(uint32_t*)&m0b; um.y = *(uint32_t*)&m1b;
            *(uint2*)(smc + A_OFF + sw)         = uh;
            *(uint2*)(smc + A_OFF + 16384 + sw) = um;
        }
        CP_WAIT0();          // B(k) landed
        __syncthreads();     // A(k) + B(k) visible
        if(k < 8){
            const char* bs = (const char*)wtb + (k+1)*16384;
            uint32_t bd = smem_base + B_OFF + ((k+1)&1)*16384;
            #pragma unroll
            for(int j = 0; j < 4; j++)
                CP_ASYNC16(bd + tid*16 + j*4096, bs + tid*16 + j*4096);
            CP_COMMIT();
        }
        const uint32_t slotB = smem_base + B_OFF + (k&1)*16384;

        #pragma unroll
        for(int ks = 0; ks < 4; ks++){
            uint32_t ca = ks*32 + aKh;
            uint32_t cb = ks*32 + bKh;
            uint32_t ah[2][4], bh[2][4];
            #pragma unroll
            for(int mi = 0; mi < 2; mi++)
                LDSM4(ah[mi], smem_base + A_OFF + aRow[mi] + (ca ^ aXor[mi]));
            #pragma unroll
            for(int ni = 0; ni < 2; ni++)
                LDSM4(bh[ni], slotB + bRow[ni] + (cb ^ bXor[ni]));
            #pragma unroll
            for(int mi = 0; mi < 2; mi++)
                #pragma unroll
                for(int n8 = 0; n8 < 4; n8++)
                    mma16816(acc[mi][n8], ah[mi], bh[n8>>1][(n8&1)*2], bh[n8>>1][(n8&1)*2+1]);
            {
                uint32_t bm[2][4];
                #pragma unroll
                for(int ni = 0; ni < 2; ni++)
                    LDSM4(bm[ni], slotB + 8192 + bRow[ni] + (cb ^ bXor[ni]));
                #pragma unroll
                for(int mi = 0; mi < 2; mi++)
                    #pragma unroll
                    for(int n8 = 0; n8 < 4; n8++)
                        mma16816(acc[mi][n8], ah[mi], bm[n8>>1][(n8&1)*2], bm[n8>>1][(n8&1)*2+1]);
            }
            {
                uint32_t am[2][4];
                #pragma unroll
                for(int mi = 0; mi < 2; mi++)
                    LDSM4(am[mi], smem_base + A_OFF + 16384 + aRow[mi] + (ca ^ aXor[mi]));
                #pragma unroll
                for(int mi = 0; mi < 2; mi++)
                    #pragma unroll
                    for(int n8 = 0; n8 < 4; n8++)
                        mma16816(acc[mi][n8], am[mi], bh[n8>>1][(n8&1)*2], bh[n8>>1][(n8&1)*2+1]);
            }
        }
        __syncthreads();   // all reads of A(k) done -> next gather may overwrite
    }

    // epilogue: BN + ReLU + store
    #pragma unroll
    for(int mi = 0; mi < 2; mi++){
        int r0 = m0 + mi*16 + (lid >> 2);
        int r1 = r0 + 8;
        #pragma unroll
        for(int n8 = 0; n8 < 4; n8++){
            int c0 = n0 + n8*8 + (lid & 3)*2;
            float iv0 = __ldg(bn + c0),      iv1 = __ldg(bn + c0 + 1);
            float bc0 = __ldg(bn + 64 + c0), bc1 = __ldg(bn + 64 + c0 + 1);
            float v00 = fmaxf(acc[mi][n8][0]*iv0 + bc0, 0.f);
            float v01 = fmaxf(acc[mi][n8][1]*iv1 + bc1, 0.f);
            float v10 = fmaxf(acc[mi][n8][2]*iv0 + bc0, 0.f);
            float v11 = fmaxf(acc[mi][n8][3]*iv1 + bc1, 0.f);
            if(NCHW_OUT){
                float* o0 = out + (((size_t)b*CH + c0)*HH + h)*WW;
                float* o1 = out + (((size_t)b*CH + c0+1)*HH + h)*WW;
                o0[r0] = v00; o1[r0] = v01;
                o0[r1] = v10; o1[r1] = v11;
            } else {
                float* base = out + ((size_t)(b*HH + h)*WW)*CH;
                *(float2*)(base + r0*CH + c0) = make_float2(v00, v01);
                *(float2*)(base + r1*CH + c0) = make_float2(v10, v11);
            }
        }
    }
}

// ---------------- launcher ----------------
extern "C" void kernel_launch(void* const* d_in, const int* in_sizes, int n_in,
                              void* d_out, int out_size)
{
    const float* x     = (const float*)d_in[0];
    const float* woff1 = (const float*)d_in[1];
    const float* boff1 = (const float*)d_in[2];
    const float* w1    = (const float*)d_in[3];
    const float* g1    = (const float*)d_in[4];
    const float* be1   = (const float*)d_in[5];
    const float* m1    = (const float*)d_in[6];
    const float* v1    = (const float*)d_in[7];
    const float* woff2 = (const float*)d_in[8];
    const float* boff2 = (const float*)d_in[9];
    const float* w2    = (const float*)d_in[10];
    const float* g2    = (const float*)d_in[11];
    const float* be2   = (const float*)d_in[12];
    const float* m2    = (const float*)d_in[13];
    const float* v2    = (const float*)d_in[14];
    float* out = (float*)d_out;

    float *xn, *y1, *offb, *bn;
    __nv_bfloat16 *wtb1, *wtb2, *wob1, *wob2;
    cudaGetSymbolAddress((void**)&xn,   g_xnhwc);
    cudaGetSymbolAddress((void**)&y1,   g_y1);
    cudaGetSymbolAddress((void**)&offb, g_off);
    cudaGetSymbolAddress((void**)&wtb1, g_wtb1);
    cudaGetSymbolAddress((void**)&wtb2, g_wtb2);
    cudaGetSymbolAddress((void**)&wob1, g_wob1);
    cudaGetSymbolAddress((void**)&wob2, g_wob2);
    cudaGetSymbolAddress((void**)&bn,   g_bn);

    cudaFuncSetAttribute(k_offt,       cudaFuncAttributeMaxDynamicSharedMemorySize, OT2_SMEM);
    cudaFuncSetAttribute(k_dcn<false>, cudaFuncAttributeMaxDynamicSharedMemorySize, DCN_SMEM);
    cudaFuncSetAttribute(k_dcn<true>,  cudaFuncAttributeMaxDynamicSharedMemorySize, DCN_SMEM);

    // launch order: k_dcn layer-1 is launch #4 (ncu effective skip = 3)
    k_prep<<<432, 256>>>(w1, w2, woff1, woff2, g1, be1, m1, v1, g2, be2, m2, v2);
    k_nchw2nhwc<<<BATCH*HH, 256>>>(x, xn);
    k_offt<<<BATCH*HH, 256, OT2_SMEM>>>(xn, wob1, boff1, offb);
    k_dcn<false><<<BATCH*HH, 256, DCN_SMEM>>>(xn, offb, wtb1, bn, y1);

    k_offt<<<BATCH*HH, 256, OT2_SMEM>>>(y1, wob2, boff2, offb);
    k_dcn<true><<<BATCH*HH, 256, DCN_SMEM>>>(y1, offb, wtb2, bn + 128, out);
}